// round 1
// baseline (speedup 1.0000x reference)
#include <cuda_runtime.h>
#include <math.h>

#define NA   4096
#define FDIM 128
#define NH   4
#define DH   32
#define KNN  15
#define NKR  50
#define NL   6
#define NEDGE (NA*KNN)

// ---------------- scratch (static device globals; no runtime alloc) --------
__device__ float d_s[NA*FDIM];
__device__ float d_o[NA*FDIM];
__device__ float d_v0[NA*3*FDIM];
__device__ float d_v1[NA*3*FDIM];
__device__ float d_qkv[NA*640];            // [q(128) | k(128) | val(384)]
__device__ float d_ekv[NEDGE*512];         // [ek(128) | ev(384)] post-silu
__device__ float d_eb[NEDGE*NKR];          // RBF edge features
__device__ float d_cut[NEDGE];
__device__ float d_vecn[NEDGE*3];
__device__ int   d_idx[NEDGE];
__device__ float d_h[NA];

// ---------------- init: s = emb[Z], o = 0, v0 = 0 ---------------------------
__global__ void init_kernel(const int* __restrict__ Z, const float* __restrict__ emb) {
    int t = blockIdx.x * blockDim.x + threadIdx.x;
    if (t < NA*FDIM) {
        int i = t / FDIM, f = t % FDIM;
        d_s[t] = emb[Z[i]*FDIM + f];
        d_o[t] = 0.f;
    }
    if (t < NA*3*FDIM) d_v0[t] = 0.f;
}

// ---------------- KNN + edge features ---------------------------------------
__global__ void knn_kernel(const float* __restrict__ R) {
    __shared__ float sd2[NA];
    __shared__ float rv[256];
    __shared__ int   rj[256];
    __shared__ int   sidx[KNN];
    __shared__ float sdd[KNN];
    __shared__ float scut[KNN];

    int i = blockIdx.x, t = threadIdx.x;
    float rx = R[i*3], ry = R[i*3+1], rz = R[i*3+2];
    float sqi = rx*rx + ry*ry + rz*rz;

    for (int j = t; j < NA; j += 256) {
        float x = R[j*3], y = R[j*3+1], z = R[j*3+2];
        float sqj = x*x + y*y + z*z;
        float dot = rx*x + ry*y + rz*z;
        float d2  = fmaxf(sqi + sqj - 2.f*dot, 0.f);
        if (j == i) d2 = 1e9f;
        sd2[j] = d2;
    }
    __syncthreads();

    for (int k = 0; k < KNN; k++) {
        float bv = 1e30f; int bj = 0x7fffffff;
        for (int j = t; j < NA; j += 256) {
            float v = sd2[j];
            if (v < bv) { bv = v; bj = j; }     // strict < keeps lowest index
        }
        rv[t] = bv; rj[t] = bj;
        __syncthreads();
        for (int s = 128; s > 0; s >>= 1) {
            if (t < s) {
                float v2 = rv[t+s]; int j2 = rj[t+s];
                if (v2 < rv[t] || (v2 == rv[t] && j2 < rj[t])) { rv[t] = v2; rj[t] = j2; }
            }
            __syncthreads();
        }
        if (t == 0) { sidx[k] = rj[0]; sd2[rj[0]] = 1e9f; }
        __syncthreads();
    }

    if (t < KNN) {
        int j = sidx[t];
        float vx = R[j*3]   - rx;
        float vy = R[j*3+1] - ry;
        float vz = R[j*3+2] - rz;
        float dd = sqrtf(vx*vx + vy*vy + vz*vz + 1e-12f);
        float inv = 1.f / dd;
        int e = i*KNN + t;
        d_idx[e] = j;
        d_vecn[e*3+0] = vx*inv;
        d_vecn[e*3+1] = vy*inv;
        d_vecn[e*3+2] = vz*inv;
        float c = (dd <= 5.f) ? 0.5f*(cosf(0.62831853071795864769f*dd) + 1.f) : 0.f;
        d_cut[e] = c;
        sdd[t] = dd; scut[t] = c;
    }
    __syncthreads();
    for (int u = t; u < KNN*NKR; u += 256) {
        int k = u / NKR, r = u % NKR;
        float mu = (float)r * (5.0f/49.0f);
        float df = sdd[k] - mu;
        d_eb[(i*KNN + k)*NKR + r] = expf(-df*df*50.f) * scut[k];   // /(2*0.1^2)
    }
}

// ---------------- QKV GEMM: (4096x128)@(128x640) ---------------------------
__global__ void qkv_gemm(const float* __restrict__ Wq, const float* __restrict__ Wk,
                         const float* __restrict__ Wv, int l) {
    __shared__ float As[16*68];
    __shared__ float Bs[16*68];
    int bm = blockIdx.x, bn = blockIdx.y, t = threadIdx.x;
    int cb = bn * 64;
    const float* B; int ldb, coff;
    if (cb < 128)       { B = Wq + l*FDIM*FDIM; ldb = FDIM; coff = cb; }
    else if (cb < 256)  { B = Wk + l*FDIM*FDIM; ldb = FDIM; coff = cb - 128; }
    else                { B = Wv + l*FDIM*384;  ldb = 384;  coff = cb - 256; }

    int tm = t >> 4, tn = t & 15;
    float acc[4][4] = {};
    for (int k0 = 0; k0 < 128; k0 += 16) {
        int lk = t & 15, lm = t >> 4;
        #pragma unroll
        for (int mm = 0; mm < 4; mm++)
            As[lk*68 + lm + mm*16] = d_s[(bm*64 + lm + mm*16)*FDIM + k0 + lk];
        #pragma unroll
        for (int u = 0; u < 4; u++) {
            int idx = t + u*256; int k = idx >> 6, n = idx & 63;
            Bs[k*68 + n] = B[(k0 + k)*ldb + coff + n];
        }
        __syncthreads();
        #pragma unroll
        for (int kk = 0; kk < 16; kk++) {
            float a[4], b[4];
            #pragma unroll
            for (int x = 0; x < 4; x++) { a[x] = As[kk*68 + tm*4 + x]; b[x] = Bs[kk*68 + tn*4 + x]; }
            #pragma unroll
            for (int ix = 0; ix < 4; ix++)
                #pragma unroll
                for (int jx = 0; jx < 4; jx++)
                    acc[ix][jx] = fmaf(a[ix], b[jx], acc[ix][jx]);
        }
        __syncthreads();
    }
    #pragma unroll
    for (int ix = 0; ix < 4; ix++)
        #pragma unroll
        for (int jx = 0; jx < 4; jx++)
            d_qkv[(bm*64 + tm*4 + ix)*640 + cb + tn*4 + jx] = acc[ix][jx];
}

// ---------------- edge filter GEMM + silu: (61440x50)@(50x512) --------------
__global__ void ekv_gemm(const float* __restrict__ Wek, const float* __restrict__ bek,
                         const float* __restrict__ Wev, const float* __restrict__ bev, int l) {
    __shared__ float As[NKR*68];
    __shared__ float Bs[NKR*68];
    int bm = blockIdx.x, bn = blockIdx.y, t = threadIdx.x;
    int cb = bn * 64;
    const float* B; const float* bias; int ldb, coff;
    if (cb < 128) { B = Wek + l*NKR*FDIM; bias = bek + l*FDIM; ldb = FDIM; coff = cb; }
    else          { B = Wev + l*NKR*384;  bias = bev + l*384;  ldb = 384;  coff = cb - 128; }

    for (int u = t; u < 64*NKR; u += 256) {
        int m = u / NKR, k = u % NKR;
        As[k*68 + m] = d_eb[(bm*64 + m)*NKR + k];
    }
    for (int u = t; u < NKR*64; u += 256) {
        int k = u / 64, n = u & 63;
        Bs[k*68 + n] = B[k*ldb + coff + n];
    }
    __syncthreads();

    int tm = t >> 4, tn = t & 15;
    float acc[4][4] = {};
    #pragma unroll
    for (int kk = 0; kk < NKR; kk++) {
        float a[4], b[4];
        #pragma unroll
        for (int x = 0; x < 4; x++) { a[x] = As[kk*68 + tm*4 + x]; b[x] = Bs[kk*68 + tn*4 + x]; }
        #pragma unroll
        for (int ix = 0; ix < 4; ix++)
            #pragma unroll
            for (int jx = 0; jx < 4; jx++)
                acc[ix][jx] = fmaf(a[ix], b[jx], acc[ix][jx]);
    }
    #pragma unroll
    for (int jx = 0; jx < 4; jx++) {
        float bb = bias[coff + tn*4 + jx];
        #pragma unroll
        for (int ix = 0; ix < 4; ix++) {
            float x = acc[ix][jx] + bb;
            float y = x / (1.f + expf(-x));      // silu
            d_ekv[(bm*64 + tm*4 + ix)*512 + cb + tn*4 + jx] = y;
        }
    }
}

// ---------------- fused attention message kernel ----------------------------
__global__ void message_kernel(const float* __restrict__ v_in, float* __restrict__ v_out) {
    __shared__ float scut[KNN];
    __shared__ float svn[KNN*3];
    __shared__ float slog[KNN*NH];
    __shared__ float sattn[KNN*NH];
    __shared__ int   sj[KNN];

    int i = blockIdx.x, f = threadIdx.x;
    int w = f >> 5, lane = f & 31;          // warp = head (DH=32)

    if (f < KNN) { int e = i*KNN + f; sj[f] = d_idx[e]; scut[f] = d_cut[e]; }
    if (f < KNN*3) svn[f] = d_vecn[i*KNN*3 + f];
    __syncthreads();

    float q = d_qkv[i*640 + f];

    // pass 1: logits
    for (int k = 0; k < KNN; k++) {
        int j = sj[k];
        float p = q * d_qkv[j*640 + 128 + f] * d_ekv[(i*KNN + k)*512 + f];
        #pragma unroll
        for (int off = 16; off; off >>= 1) p += __shfl_down_sync(0xffffffffu, p, off);
        if (lane == 0) slog[k*NH + w] = p * 0.125f;   // 1/sqrt(DH*TEMP) = 1/8
    }
    __syncthreads();

    // softmax over k per head, times cutoff
    {
        float lv = (lane < KNN) ? slog[lane*NH + w] : -1e30f;
        float mx = lv;
        #pragma unroll
        for (int off = 16; off; off >>= 1) mx = fmaxf(mx, __shfl_xor_sync(0xffffffffu, mx, off));
        float ex = (lane < KNN) ? expf(lv - mx) : 0.f;
        float sm = ex;
        #pragma unroll
        for (int off = 16; off; off >>= 1) sm += __shfl_xor_sync(0xffffffffu, sm, off);
        if (lane < KNN) sattn[lane*NH + w] = ex / sm * scut[lane];
    }
    __syncthreads();

    // pass 2: messages
    float ds = 0.f, dv0 = 0.f, dv1 = 0.f, dv2 = 0.f;
    for (int k = 0; k < KNN; k++) {
        int j  = sj[k];
        float wf = sattn[k*NH + w];
        int eb = (i*KNN + k)*512;
        int jb = j*640;
        float m1 = d_qkv[jb + 256 + f] * d_ekv[eb + 128 + f];
        float m2 = d_qkv[jb + 384 + f] * d_ekv[eb + 256 + f];
        float m3 = d_qkv[jb + 512 + f] * d_ekv[eb + 384 + f];
        ds += wf * m1;
        float wm2 = wf * m2, wm3 = wf * m3;
        dv0 = fmaf(wm2, svn[k*3+0], fmaf(wm3, v_in[j*384 +        f], dv0));
        dv1 = fmaf(wm2, svn[k*3+1], fmaf(wm3, v_in[j*384 + 128 +  f], dv1));
        dv2 = fmaf(wm2, svn[k*3+2], fmaf(wm3, v_in[j*384 + 256 +  f], dv2));
    }
    d_s[i*FDIM + f] += ds;
    d_o[i*FDIM + f] += ds;
    v_out[i*384 +        f] = v_in[i*384 +        f] + dv0;
    v_out[i*384 + 128 +  f] = v_in[i*384 + 128 +  f] + dv1;
    v_out[i*384 + 256 +  f] = v_in[i*384 + 256 +  f] + dv2;
}

// ---------------- layernorm + readout ---------------------------------------
__global__ void readout_kernel(const float* __restrict__ ln_g, const float* __restrict__ ln_b,
                               const float* __restrict__ Wo1,  const float* __restrict__ Wo2) {
    __shared__ float red[128];
    __shared__ float son[128];
    int i = blockIdx.x, f = threadIdx.x;
    float x = d_o[i*FDIM + f];

    red[f] = x; __syncthreads();
    for (int s = 64; s > 0; s >>= 1) { if (f < s) red[f] += red[f+s]; __syncthreads(); }
    float mean = red[0] * (1.f/128.f);
    __syncthreads();

    float dx = x - mean;
    red[f] = dx*dx; __syncthreads();
    for (int s = 64; s > 0; s >>= 1) { if (f < s) red[f] += red[f+s]; __syncthreads(); }
    float var = red[0] * (1.f/128.f);
    __syncthreads();

    float on = dx * (1.f / sqrtf(var + 1e-5f)) * ln_g[f] + ln_b[f];
    son[f] = on; __syncthreads();

    float acc = 0.f;
    #pragma unroll 8
    for (int g = 0; g < 128; g++) acc = fmaf(son[g], Wo1[g*FDIM + f], acc);
    float tb = acc / (1.f + expf(-acc));     // silu
    red[f] = tb * Wo2[f];
    __syncthreads();
    for (int s = 64; s > 0; s >>= 1) { if (f < s) red[f] += red[f+s]; __syncthreads(); }
    if (f == 0) d_h[i] = red[0];
}

__global__ void sum_kernel(float* __restrict__ out) {
    __shared__ double rd[256];
    int t = threadIdx.x;
    double a = 0.0;
    for (int i = t; i < NA; i += 256) a += (double)d_h[i];
    rd[t] = a; __syncthreads();
    for (int s = 128; s > 0; s >>= 1) { if (t < s) rd[t] += rd[t+s]; __syncthreads(); }
    if (t == 0) out[0] = (float)rd[0];
}

// ---------------- launch ------------------------------------------------------
extern "C" void kernel_launch(void* const* d_in, const int* in_sizes, int n_in,
                              void* d_out, int out_size) {
    const int*   Z    = (const int*)  d_in[0];
    const float* R    = (const float*)d_in[1];
    // d_in[2] = batch (all ones; unused beyond the implicit sum weighting)
    const float* emb  = (const float*)d_in[3];
    const float* Wq   = (const float*)d_in[4];
    const float* Wk   = (const float*)d_in[5];
    const float* Wv   = (const float*)d_in[6];
    const float* We_k = (const float*)d_in[7];
    const float* be_k = (const float*)d_in[8];
    const float* We_v = (const float*)d_in[9];
    const float* be_v = (const float*)d_in[10];
    const float* ln_g = (const float*)d_in[11];
    const float* ln_b = (const float*)d_in[12];
    const float* Wo1  = (const float*)d_in[13];
    const float* Wo2  = (const float*)d_in[14];
    float* out = (float*)d_out;

    init_kernel<<<(NA*3*FDIM + 255)/256, 256>>>(Z, emb);
    knn_kernel<<<NA, 256>>>(R);

    float* vbufs[2];
    // resolve device symbol addresses once per launch via kernel args is not
    // possible for __device__ arrays directly from host; use cudaGetSymbolAddress.
    static float* v0p = nullptr;
    static float* v1p = nullptr;
    if (!v0p) {
        cudaGetSymbolAddress((void**)&v0p, d_v0);
        cudaGetSymbolAddress((void**)&v1p, d_v1);
    }
    vbufs[0] = v0p; vbufs[1] = v1p;

    for (int l = 0; l < NL; l++) {
        qkv_gemm<<<dim3(NA/64, 10), 256>>>(Wq, Wk, Wv, l);
        ekv_gemm<<<dim3(NEDGE/64, 8), 256>>>(We_k, be_k, We_v, be_v, l);
        message_kernel<<<NA, 128>>>(vbufs[l & 1], vbufs[(l + 1) & 1]);
    }

    readout_kernel<<<NA, 128>>>(ln_g, ln_b, Wo1, Wo2);
    sum_kernel<<<1, 256>>>(out);
}

// round 2
// speedup vs baseline: 1.1902x; 1.1902x over previous
#include <cuda_runtime.h>
#include <math.h>

#define NA   4096
#define FDIM 128
#define NH   4
#define DH   32
#define KNN  15
#define NKR  50
#define NL   6
#define NEDGE (NA*KNN)
#define WT   16            // RBF window taps
#define EB   64            // edges per ekv block

// ---------------- scratch (static device globals; no runtime alloc) --------
__device__ float d_s[NA*FDIM];
__device__ float d_o[NA*FDIM];
__device__ float d_v0[NA*3*FDIM];
__device__ float d_v1[NA*3*FDIM];
__device__ float d_qkv[NA*640];            // [q(128) | k(128) | val(384)]
__device__ float d_ekv[NEDGE*512];         // [ek(128) | ev(384)] post-silu
__device__ float d_cut[NEDGE];
__device__ float d_dist[NEDGE];
__device__ float d_vecn[NEDGE*3];
__device__ int   d_idx[NEDGE];
__device__ float d_h[NA];

// ---------------- init: s = emb[Z], o = 0, v0 = 0 ---------------------------
__global__ void init_kernel(const int* __restrict__ Z, const float* __restrict__ emb) {
    int t = blockIdx.x * blockDim.x + threadIdx.x;
    if (t < NA*FDIM) {
        int i = t / FDIM, f = t % FDIM;
        d_s[t] = emb[Z[i]*FDIM + f];
        d_o[t] = 0.f;
    }
    if (t < NA*3*FDIM) d_v0[t] = 0.f;
}

// ---------------- KNN + edge geometry ---------------------------------------
__global__ void knn_kernel(const float* __restrict__ R) {
    __shared__ float sd2[NA];
    __shared__ float rv[256];
    __shared__ int   rj[256];
    __shared__ int   sidx[KNN];

    int i = blockIdx.x, t = threadIdx.x;
    float rx = R[i*3], ry = R[i*3+1], rz = R[i*3+2];
    float sqi = rx*rx + ry*ry + rz*rz;

    for (int j = t; j < NA; j += 256) {
        float x = R[j*3], y = R[j*3+1], z = R[j*3+2];
        float sqj = x*x + y*y + z*z;
        float dot = rx*x + ry*y + rz*z;
        float d2  = fmaxf(sqi + sqj - 2.f*dot, 0.f);
        if (j == i) d2 = 1e9f;
        sd2[j] = d2;
    }
    __syncthreads();

    for (int k = 0; k < KNN; k++) {
        float bv = 1e30f; int bj = 0x7fffffff;
        for (int j = t; j < NA; j += 256) {
            float v = sd2[j];
            if (v < bv) { bv = v; bj = j; }     // strict < keeps lowest index
        }
        rv[t] = bv; rj[t] = bj;
        __syncthreads();
        for (int s = 128; s > 0; s >>= 1) {
            if (t < s) {
                float v2 = rv[t+s]; int j2 = rj[t+s];
                if (v2 < rv[t] || (v2 == rv[t] && j2 < rj[t])) { rv[t] = v2; rj[t] = j2; }
            }
            __syncthreads();
        }
        if (t == 0) { sidx[k] = rj[0]; sd2[rj[0]] = 1e9f; }
        __syncthreads();
    }

    if (t < KNN) {
        int j = sidx[t];
        float vx = R[j*3]   - rx;
        float vy = R[j*3+1] - ry;
        float vz = R[j*3+2] - rz;
        float dd = sqrtf(vx*vx + vy*vy + vz*vz + 1e-12f);
        float inv = 1.f / dd;
        int e = i*KNN + t;
        d_idx[e] = j;
        d_vecn[e*3+0] = vx*inv;
        d_vecn[e*3+1] = vy*inv;
        d_vecn[e*3+2] = vz*inv;
        float c = (dd <= 5.f) ? 0.5f*(cosf(0.62831853071795864769f*dd) + 1.f) : 0.f;
        d_cut[e]  = c;
        d_dist[e] = dd;
    }
}

// ---------------- QKV GEMM: (4096x128)@(128x640), 128x64 tiles --------------
__global__ __launch_bounds__(256) void qkv_gemm(const float* __restrict__ Wq,
                                                const float* __restrict__ Wk,
                                                const float* __restrict__ Wv, int l) {
    __shared__ float As[8*128];   // [k][m]
    __shared__ float Bs[8*64];    // [k][n]
    int bm = blockIdx.x, bn = blockIdx.y, t = threadIdx.x;
    int m0 = bm * 128;
    int cb = bn * 64;
    const float* B; int ldb, coff;
    if (cb < 128)       { B = Wq + l*FDIM*FDIM; ldb = FDIM; coff = cb; }
    else if (cb < 256)  { B = Wk + l*FDIM*FDIM; ldb = FDIM; coff = cb - 128; }
    else                { B = Wv + l*FDIM*384;  ldb = 384;  coff = cb - 256; }

    int tx = t & 15;      // n: 4 cols
    int ty = t >> 4;      // m: 8 rows
    float acc[8][4] = {};

    for (int k0 = 0; k0 < 128; k0 += 8) {
        {
            int k = t & 7, mb = t >> 3;
            #pragma unroll
            for (int p = 0; p < 4; p++) {
                int m = mb + p*32;
                As[k*128 + m] = d_s[(m0 + m)*FDIM + k0 + k];
            }
            if (t < 128) {
                int kk = t >> 4, n4 = t & 15;
                *(float4*)&Bs[kk*64 + n4*4] =
                    *(const float4*)&B[(k0 + kk)*ldb + coff + n4*4];
            }
        }
        __syncthreads();
        #pragma unroll
        for (int kk = 0; kk < 8; kk++) {
            float a[8], b[4];
            #pragma unroll
            for (int x = 0; x < 8; x++) a[x] = As[kk*128 + ty*8 + x];
            #pragma unroll
            for (int x = 0; x < 4; x++) b[x] = Bs[kk*64 + tx*4 + x];
            #pragma unroll
            for (int ix = 0; ix < 8; ix++)
                #pragma unroll
                for (int jx = 0; jx < 4; jx++)
                    acc[ix][jx] = fmaf(a[ix], b[jx], acc[ix][jx]);
        }
        __syncthreads();
    }
    #pragma unroll
    for (int ix = 0; ix < 8; ix++) {
        float4 v = make_float4(acc[ix][0], acc[ix][1], acc[ix][2], acc[ix][3]);
        *(float4*)&d_qkv[(m0 + ty*8 + ix)*640 + cb + tx*4] = v;
    }
}

// ---------------- windowed edge filter + silu --------------------------------
// e@W where e is a 50-wide Gaussian RBF row: only a 16-tap window around
// round(d/step) is non-negligible (dropped taps < 2e-13). W (50x512) lives in
// smem; 4 distance-sorted edges share each W-row read over their window union.
#define EKV_SMEM (50*512*4 + EB*WT*4 + EB*4)

__global__ __launch_bounds__(256) void ekv_kernel(const float* __restrict__ Wek,
                                                  const float* __restrict__ bek,
                                                  const float* __restrict__ Wev,
                                                  const float* __restrict__ bev, int l) {
    extern __shared__ float sm[];
    float* Ws  = sm;                       // 50*512
    float* ews = sm + 50*512;              // EB*WT
    int*   kb  = (int*)(ews + EB*WT);      // EB

    int tid = threadIdx.x;
    int ebase0 = blockIdx.x * EB;

    // load combined weight matrix [50][512] = [We_k(128) | We_v(384)]
    {
        float4* Ws4 = (float4*)Ws;
        const float4* Wek4 = (const float4*)(Wek + l*50*FDIM);
        const float4* Wev4 = (const float4*)(Wev + l*50*384);
        for (int q = tid; q < 50*128; q += 256) {
            int row = q >> 7;
            int c4  = q & 127;
            float4 v;
            if (c4 < 32) v = Wek4[row*32 + c4];
            else         v = Wev4[row*96 + (c4 - 32)];
            Ws4[q] = v;
        }
    }
    // per-edge window base + tap weights
    for (int u = tid; u < EB*WT; u += 256) {
        int e = u >> 4, tt = u & 15;
        int ge = ebase0 + e;
        float dd = d_dist[ge], c = d_cut[ge];
        float fi = dd * (49.0f/5.0f);
        int k0 = (int)floorf(fi + 0.5f) - 7;
        k0 = max(0, min(50 - WT, k0));
        if (tt == 0) kb[e] = k0;
        float mu = (float)(k0 + tt) * (5.0f/49.0f);
        float df = dd - mu;
        ews[u] = expf(-df*df*50.0f) * c;
    }
    __syncthreads();

    int cg = tid & 63;        // column group: cols cg*4..+3 and 256+cg*4..+3
    int eg = tid >> 6;        // edge super-group 0..3
    int c0 = cg * 4;

    float4 bias0 = (c0 < 128) ? *(const float4*)&bek[l*FDIM + c0]
                              : *(const float4*)&bev[l*384 + (c0 - 128)];
    float4 bias1 = *(const float4*)&bev[l*384 + (128 + c0)];

    #pragma unroll
    for (int gi = 0; gi < 4; gi++) {
        int g = eg*4 + gi;
        int ebase = g*4;
        int kbv[4];
        #pragma unroll
        for (int e = 0; e < 4; e++) kbv[e] = kb[ebase + e];
        int rmin = min(min(kbv[0], kbv[1]), min(kbv[2], kbv[3]));
        int rmax = max(max(kbv[0], kbv[1]), max(kbv[2], kbv[3])) + WT;

        float acc[4][8] = {};
        for (int r = rmin; r < rmax; r++) {
            const float* wr = &Ws[r*512 + c0];
            float4 w0 = *(const float4*)wr;
            float4 w1 = *(const float4*)(wr + 256);
            #pragma unroll
            for (int e = 0; e < 4; e++) {
                unsigned tt = (unsigned)(r - kbv[e]);
                float cw = (tt < (unsigned)WT) ? ews[(ebase + e)*WT + tt] : 0.f;
                acc[e][0] = fmaf(cw, w0.x, acc[e][0]);
                acc[e][1] = fmaf(cw, w0.y, acc[e][1]);
                acc[e][2] = fmaf(cw, w0.z, acc[e][2]);
                acc[e][3] = fmaf(cw, w0.w, acc[e][3]);
                acc[e][4] = fmaf(cw, w1.x, acc[e][4]);
                acc[e][5] = fmaf(cw, w1.y, acc[e][5]);
                acc[e][6] = fmaf(cw, w1.z, acc[e][6]);
                acc[e][7] = fmaf(cw, w1.w, acc[e][7]);
            }
        }
        #pragma unroll
        for (int e = 0; e < 4; e++) {
            int ge = ebase0 + ebase + e;
            float* out = d_ekv + (size_t)ge*512;
            float x0 = acc[e][0] + bias0.x, x1 = acc[e][1] + bias0.y;
            float x2 = acc[e][2] + bias0.z, x3 = acc[e][3] + bias0.w;
            float y0 = acc[e][4] + bias1.x, y1 = acc[e][5] + bias1.y;
            float y2 = acc[e][6] + bias1.z, y3 = acc[e][7] + bias1.w;
            float4 o0 = make_float4(x0/(1.f+expf(-x0)), x1/(1.f+expf(-x1)),
                                    x2/(1.f+expf(-x2)), x3/(1.f+expf(-x3)));
            float4 o1 = make_float4(y0/(1.f+expf(-y0)), y1/(1.f+expf(-y1)),
                                    y2/(1.f+expf(-y2)), y3/(1.f+expf(-y3)));
            *(float4*)(out + c0)       = o0;
            *(float4*)(out + 256 + c0) = o1;
        }
    }
}

// ---------------- fused attention message kernel ----------------------------
__global__ void message_kernel(const float* __restrict__ v_in, float* __restrict__ v_out) {
    __shared__ float scut[KNN];
    __shared__ float svn[KNN*3];
    __shared__ float slog[KNN*NH];
    __shared__ float sattn[KNN*NH];
    __shared__ int   sj[KNN];

    int i = blockIdx.x, f = threadIdx.x;
    int w = f >> 5, lane = f & 31;          // warp = head (DH=32)

    if (f < KNN) { int e = i*KNN + f; sj[f] = d_idx[e]; scut[f] = d_cut[e]; }
    if (f < KNN*3) svn[f] = d_vecn[i*KNN*3 + f];
    __syncthreads();

    float q = d_qkv[i*640 + f];

    // pass 1: logits
    for (int k = 0; k < KNN; k++) {
        int j = sj[k];
        float p = q * d_qkv[j*640 + 128 + f] * d_ekv[(size_t)(i*KNN + k)*512 + f];
        #pragma unroll
        for (int off = 16; off; off >>= 1) p += __shfl_down_sync(0xffffffffu, p, off);
        if (lane == 0) slog[k*NH + w] = p * 0.125f;   // 1/sqrt(DH*TEMP) = 1/8
    }
    __syncthreads();

    // softmax over k per head, times cutoff
    {
        float lv = (lane < KNN) ? slog[lane*NH + w] : -1e30f;
        float mx = lv;
        #pragma unroll
        for (int off = 16; off; off >>= 1) mx = fmaxf(mx, __shfl_xor_sync(0xffffffffu, mx, off));
        float ex = (lane < KNN) ? expf(lv - mx) : 0.f;
        float sm = ex;
        #pragma unroll
        for (int off = 16; off; off >>= 1) sm += __shfl_xor_sync(0xffffffffu, sm, off);
        if (lane < KNN) sattn[lane*NH + w] = ex / sm * scut[lane];
    }
    __syncthreads();

    // pass 2: messages
    float ds = 0.f, dv0 = 0.f, dv1 = 0.f, dv2 = 0.f;
    for (int k = 0; k < KNN; k++) {
        int j  = sj[k];
        float wf = sattn[k*NH + w];
        size_t eb = (size_t)(i*KNN + k)*512;
        int jb = j*640;
        float m1 = d_qkv[jb + 256 + f] * d_ekv[eb + 128 + f];
        float m2 = d_qkv[jb + 384 + f] * d_ekv[eb + 256 + f];
        float m3 = d_qkv[jb + 512 + f] * d_ekv[eb + 384 + f];
        ds += wf * m1;
        float wm2 = wf * m2, wm3 = wf * m3;
        dv0 = fmaf(wm2, svn[k*3+0], fmaf(wm3, v_in[j*384 +        f], dv0));
        dv1 = fmaf(wm2, svn[k*3+1], fmaf(wm3, v_in[j*384 + 128 +  f], dv1));
        dv2 = fmaf(wm2, svn[k*3+2], fmaf(wm3, v_in[j*384 + 256 +  f], dv2));
    }
    d_s[i*FDIM + f] += ds;
    d_o[i*FDIM + f] += ds;
    v_out[i*384 +        f] = v_in[i*384 +        f] + dv0;
    v_out[i*384 + 128 +  f] = v_in[i*384 + 128 +  f] + dv1;
    v_out[i*384 + 256 +  f] = v_in[i*384 + 256 +  f] + dv2;
}

// ---------------- layernorm + readout ---------------------------------------
__global__ void readout_kernel(const float* __restrict__ ln_g, const float* __restrict__ ln_b,
                               const float* __restrict__ Wo1,  const float* __restrict__ Wo2) {
    __shared__ float red[128];
    __shared__ float son[128];
    int i = blockIdx.x, f = threadIdx.x;
    float x = d_o[i*FDIM + f];

    red[f] = x; __syncthreads();
    for (int s = 64; s > 0; s >>= 1) { if (f < s) red[f] += red[f+s]; __syncthreads(); }
    float mean = red[0] * (1.f/128.f);
    __syncthreads();

    float dx = x - mean;
    red[f] = dx*dx; __syncthreads();
    for (int s = 64; s > 0; s >>= 1) { if (f < s) red[f] += red[f+s]; __syncthreads(); }
    float var = red[0] * (1.f/128.f);
    __syncthreads();

    float on = dx * (1.f / sqrtf(var + 1e-5f)) * ln_g[f] + ln_b[f];
    son[f] = on; __syncthreads();

    float acc = 0.f;
    #pragma unroll 8
    for (int g = 0; g < 128; g++) acc = fmaf(son[g], Wo1[g*FDIM + f], acc);
    float tb = acc / (1.f + expf(-acc));     // silu
    red[f] = tb * Wo2[f];
    __syncthreads();
    for (int s = 64; s > 0; s >>= 1) { if (f < s) red[f] += red[f+s]; __syncthreads(); }
    if (f == 0) d_h[i] = red[0];
}

__global__ void sum_kernel(float* __restrict__ out) {
    __shared__ double rd[256];
    int t = threadIdx.x;
    double a = 0.0;
    for (int i = t; i < NA; i += 256) a += (double)d_h[i];
    rd[t] = a; __syncthreads();
    for (int s = 128; s > 0; s >>= 1) { if (t < s) rd[t] += rd[t+s]; __syncthreads(); }
    if (t == 0) out[0] = (float)rd[0];
}

// ---------------- launch ------------------------------------------------------
extern "C" void kernel_launch(void* const* d_in, const int* in_sizes, int n_in,
                              void* d_out, int out_size) {
    const int*   Z    = (const int*)  d_in[0];
    const float* R    = (const float*)d_in[1];
    const float* emb  = (const float*)d_in[3];
    const float* Wq   = (const float*)d_in[4];
    const float* Wk   = (const float*)d_in[5];
    const float* Wv   = (const float*)d_in[6];
    const float* We_k = (const float*)d_in[7];
    const float* be_k = (const float*)d_in[8];
    const float* We_v = (const float*)d_in[9];
    const float* be_v = (const float*)d_in[10];
    const float* ln_g = (const float*)d_in[11];
    const float* ln_b = (const float*)d_in[12];
    const float* Wo1  = (const float*)d_in[13];
    const float* Wo2  = (const float*)d_in[14];
    float* out = (float*)d_out;

    static float* v0p = nullptr;
    static float* v1p = nullptr;
    static bool attr_done = false;
    if (!v0p) {
        cudaGetSymbolAddress((void**)&v0p, d_v0);
        cudaGetSymbolAddress((void**)&v1p, d_v1);
    }
    if (!attr_done) {
        cudaFuncSetAttribute(ekv_kernel, cudaFuncAttributeMaxDynamicSharedMemorySize, EKV_SMEM);
        attr_done = true;
    }
    float* vbufs[2] = { v0p, v1p };

    init_kernel<<<(NA*3*FDIM + 255)/256, 256>>>(Z, emb);
    knn_kernel<<<NA, 256>>>(R);

    for (int l = 0; l < NL; l++) {
        qkv_gemm<<<dim3(NA/128, 10), 256>>>(Wq, Wk, Wv, l);
        ekv_kernel<<<NEDGE/EB, 256, EKV_SMEM>>>(We_k, be_k, We_v, be_v, l);
        message_kernel<<<NA, 128>>>(vbufs[l & 1], vbufs[(l + 1) & 1]);
    }

    readout_kernel<<<NA, 128>>>(ln_g, ln_b, Wo1, Wo2);
    sum_kernel<<<1, 256>>>(out);
}

// round 3
// speedup vs baseline: 1.2908x; 1.0846x over previous
#include <cuda_runtime.h>
#include <math.h>

#define NA   4096
#define FDIM 128
#define NH   4
#define DH   32
#define KNN  15
#define NKR  50
#define NL   6
#define NEDGE (NA*KNN)
#define WT   16            // RBF window taps

// ekv kernel tiling
#define EKV_EB    128      // edges per block
#define EKV_EPASS 32       // edges per pass (8 groups of 4)
#define EKV_NPASS (EKV_EB/EKV_EPASS)
#define EKV_NGRP  8        // warps per block == groups per pass
#define RPAD      50       // padded rows per group (exact: span <= 50 always)

// ---------------- scratch (static device globals; no runtime alloc) --------
__device__ float d_s[NA*FDIM];
__device__ float d_o[NA*FDIM];
__device__ float d_v0[NA*3*FDIM];
__device__ float d_v1[NA*3*FDIM];
__device__ float d_qkv[NA*640];            // [q(128) | k(128) | val(384)]
__device__ float d_ekv[NEDGE*512];         // [ek(128) | ev(384)] post-silu
__device__ float d_cut[NEDGE];
__device__ float d_dist[NEDGE];
__device__ float d_vecn[NEDGE*3];
__device__ int   d_idx[NEDGE];
__device__ float d_h[NA];

// ---------------- init: s = emb[Z], o = 0, v0 = 0 ---------------------------
__global__ void init_kernel(const int* __restrict__ Z, const float* __restrict__ emb) {
    int t = blockIdx.x * blockDim.x + threadIdx.x;
    if (t < NA*FDIM) {
        int i = t / FDIM, f = t % FDIM;
        d_s[t] = emb[Z[i]*FDIM + f];
        d_o[t] = 0.f;
    }
    if (t < NA*3*FDIM) d_v0[t] = 0.f;
}

// ---------------- KNN + edge geometry ---------------------------------------
__global__ void knn_kernel(const float* __restrict__ R) {
    __shared__ float sd2[NA];
    __shared__ float rv[256];
    __shared__ int   rj[256];
    __shared__ int   sidx[KNN];

    int i = blockIdx.x, t = threadIdx.x;
    float rx = R[i*3], ry = R[i*3+1], rz = R[i*3+2];
    float sqi = rx*rx + ry*ry + rz*rz;

    for (int j = t; j < NA; j += 256) {
        float x = R[j*3], y = R[j*3+1], z = R[j*3+2];
        float sqj = x*x + y*y + z*z;
        float dot = rx*x + ry*y + rz*z;
        float d2  = fmaxf(sqi + sqj - 2.f*dot, 0.f);
        if (j == i) d2 = 1e9f;
        sd2[j] = d2;
    }
    __syncthreads();

    for (int k = 0; k < KNN; k++) {
        float bv = 1e30f; int bj = 0x7fffffff;
        for (int j = t; j < NA; j += 256) {
            float v = sd2[j];
            if (v < bv) { bv = v; bj = j; }     // strict < keeps lowest index
        }
        rv[t] = bv; rj[t] = bj;
        __syncthreads();
        for (int s = 128; s > 0; s >>= 1) {
            if (t < s) {
                float v2 = rv[t+s]; int j2 = rj[t+s];
                if (v2 < rv[t] || (v2 == rv[t] && j2 < rj[t])) { rv[t] = v2; rj[t] = j2; }
            }
            __syncthreads();
        }
        if (t == 0) { sidx[k] = rj[0]; sd2[rj[0]] = 1e9f; }
        __syncthreads();
    }

    if (t < KNN) {
        int j = sidx[t];
        float vx = R[j*3]   - rx;
        float vy = R[j*3+1] - ry;
        float vz = R[j*3+2] - rz;
        float dd = sqrtf(vx*vx + vy*vy + vz*vz + 1e-12f);
        float inv = 1.f / dd;
        int e = i*KNN + t;
        d_idx[e] = j;
        d_vecn[e*3+0] = vx*inv;
        d_vecn[e*3+1] = vy*inv;
        d_vecn[e*3+2] = vz*inv;
        float c = (dd <= 5.f) ? 0.5f*(cosf(0.62831853071795864769f*dd) + 1.f) : 0.f;
        d_cut[e]  = c;
        d_dist[e] = dd;
    }
}

// ---------------- QKV GEMM: (4096x128)@(128x640), 128x64 tiles --------------
__global__ __launch_bounds__(256) void qkv_gemm(const float* __restrict__ Wq,
                                                const float* __restrict__ Wk,
                                                const float* __restrict__ Wv, int l) {
    __shared__ float As[8*128];   // [k][m]
    __shared__ float Bs[8*64];    // [k][n]
    int bm = blockIdx.x, bn = blockIdx.y, t = threadIdx.x;
    int m0 = bm * 128;
    int cb = bn * 64;
    const float* B; int ldb, coff;
    if (cb < 128)       { B = Wq + l*FDIM*FDIM; ldb = FDIM; coff = cb; }
    else if (cb < 256)  { B = Wk + l*FDIM*FDIM; ldb = FDIM; coff = cb - 128; }
    else                { B = Wv + l*FDIM*384;  ldb = 384;  coff = cb - 256; }

    int tx = t & 15;      // n: 4 cols
    int ty = t >> 4;      // m: 8 rows
    float acc[8][4] = {};

    for (int k0 = 0; k0 < 128; k0 += 8) {
        {
            int k = t & 7, mb = t >> 3;
            #pragma unroll
            for (int p = 0; p < 4; p++) {
                int m = mb + p*32;
                As[k*128 + m] = d_s[(m0 + m)*FDIM + k0 + k];
            }
            if (t < 128) {
                int kk = t >> 4, n4 = t & 15;
                *(float4*)&Bs[kk*64 + n4*4] =
                    *(const float4*)&B[(k0 + kk)*ldb + coff + n4*4];
            }
        }
        __syncthreads();
        #pragma unroll
        for (int kk = 0; kk < 8; kk++) {
            float a[8], b[4];
            #pragma unroll
            for (int x = 0; x < 8; x++) a[x] = As[kk*128 + ty*8 + x];
            #pragma unroll
            for (int x = 0; x < 4; x++) b[x] = Bs[kk*64 + tx*4 + x];
            #pragma unroll
            for (int ix = 0; ix < 8; ix++)
                #pragma unroll
                for (int jx = 0; jx < 4; jx++)
                    acc[ix][jx] = fmaf(a[ix], b[jx], acc[ix][jx]);
        }
        __syncthreads();
    }
    #pragma unroll
    for (int ix = 0; ix < 8; ix++) {
        float4 v = make_float4(acc[ix][0], acc[ix][1], acc[ix][2], acc[ix][3]);
        *(float4*)&d_qkv[(m0 + ty*8 + ix)*640 + cb + tx*4] = v;
    }
}

// ---------------- windowed edge filter + silu (zero-padded tap scatter) -----
// smem layout (floats):
//   Ws      [50*512]                    102400 B
//   ewspad  [NGRP*RPAD*4]                 6400 B
//   biasS   [512]                         2048 B
//   kbs     [32] (int) | dds[32] | cuts[32] | rminS[8] (int) | spanS[8] (int)
#define EKV_SM_WS    0
#define EKV_SM_EWS   (50*512)
#define EKV_SM_BIAS  (EKV_SM_EWS + EKV_NGRP*RPAD*4)
#define EKV_SM_KBS   (EKV_SM_BIAS + 512)
#define EKV_SM_DDS   (EKV_SM_KBS + 32)
#define EKV_SM_CUTS  (EKV_SM_DDS + 32)
#define EKV_SM_RMIN  (EKV_SM_CUTS + 32)
#define EKV_SM_SPAN  (EKV_SM_RMIN + 8)
#define EKV_SMEM     ((EKV_SM_SPAN + 8) * 4)

__global__ __launch_bounds__(256, 2) void ekv_kernel(const float* __restrict__ Wek,
                                                     const float* __restrict__ bek,
                                                     const float* __restrict__ Wev,
                                                     const float* __restrict__ bev, int l) {
    extern __shared__ float sm[];
    float* Ws    = sm + EKV_SM_WS;
    float* ews   = sm + EKV_SM_EWS;
    float* biasS = sm + EKV_SM_BIAS;
    int*   kbs   = (int*)(sm + EKV_SM_KBS);
    float* dds   = sm + EKV_SM_DDS;
    float* cuts  = sm + EKV_SM_CUTS;
    int*   rminS = (int*)(sm + EKV_SM_RMIN);
    int*   spanS = (int*)(sm + EKV_SM_SPAN);

    int tid  = threadIdx.x;
    int lane = tid & 31;
    int g    = tid >> 5;                    // warp == group
    int eblk = blockIdx.x * EKV_EB;

    // load combined weight matrix [50][512] = [We_k(128) | We_v(384)] + bias
    {
        float4* Ws4 = (float4*)Ws;
        const float4* Wek4 = (const float4*)(Wek + l*50*FDIM);
        const float4* Wev4 = (const float4*)(Wev + l*50*384);
        for (int q = tid; q < 50*128; q += 256) {
            int row = q >> 7;
            int c4  = q & 127;
            Ws4[q] = (c4 < 32) ? Wek4[row*32 + c4] : Wev4[row*96 + (c4 - 32)];
        }
        if (tid < 128) {
            float4 b = (tid < 32) ? ((const float4*)(bek + l*FDIM))[tid]
                                  : ((const float4*)(bev + l*384))[tid - 32];
            ((float4*)biasS)[tid] = b;
        }
    }

    int c0 = lane * 4;

    for (int pass = 0; pass < EKV_NPASS; pass++) {
        int e0 = eblk + pass * EKV_EPASS;
        __syncthreads();                    // Ws/bias ready; prev compute done

        // zero tap pad
        {
            float4 z = make_float4(0.f, 0.f, 0.f, 0.f);
            for (int u = tid; u < EKV_NGRP*RPAD; u += 256)
                ((float4*)ews)[u] = z;
        }
        // per-edge window base
        if (tid < EKV_EPASS) {
            int ge = e0 + tid;
            float dd = d_dist[ge];
            float fi = dd * (49.0f/5.0f);
            int k0 = (int)floorf(fi + 0.5f) - 7;
            k0 = max(0, min(50 - WT, k0));
            kbs[tid]  = k0;
            dds[tid]  = dd;
            cuts[tid] = d_cut[ge];
        }
        __syncthreads();
        if (tid < EKV_NGRP) {
            int a0 = kbs[tid*4], a1 = kbs[tid*4+1], a2 = kbs[tid*4+2], a3 = kbs[tid*4+3];
            int rmin = min(min(a0,a1), min(a2,a3));
            int rmax = max(max(a0,a1), max(a2,a3)) + WT;
            rminS[tid] = rmin;
            spanS[tid] = rmax - rmin;
        }
        __syncthreads();
        // scatter 16 taps per edge into padded array
        for (int u = tid; u < EKV_EPASS*WT; u += 256) {
            int e = u >> 4, tt = u & 15;
            int gg = e >> 2;
            int kk = kbs[e];
            int row = kk + tt - rminS[gg];
            float mu = (float)(kk + tt) * (5.0f/49.0f);
            float df = dds[e] - mu;
            ews[(gg*RPAD + row)*4 + (e & 3)] = __expf(-df*df*50.0f) * cuts[e];
        }
        __syncthreads();

        // compute: warp g handles its 4 edges, thread covers cols c0,+128,+256,+384
        int rmin = rminS[g];
        int span = spanS[g];
        const float* wp = Ws + rmin*512 + c0;
        const float4* ep = (const float4*)(ews + g*RPAD*4);

        float4 a00 = make_float4(0,0,0,0), a01 = a00, a02 = a00, a03 = a00;
        float4 a10 = a00, a11 = a00, a12 = a00, a13 = a00;
        float4 a20 = a00, a21 = a00, a22 = a00, a23 = a00;
        float4 a30 = a00, a31 = a00, a32 = a00, a33 = a00;

        for (int r = 0; r < span; r++) {
            float4 ew = ep[r];
            float4 w0 = *(const float4*)(wp);
            float4 w1 = *(const float4*)(wp + 128);
            float4 w2 = *(const float4*)(wp + 256);
            float4 w3 = *(const float4*)(wp + 384);
            wp += 512;
            a00.x = fmaf(ew.x, w0.x, a00.x); a00.y = fmaf(ew.x, w0.y, a00.y);
            a00.z = fmaf(ew.x, w0.z, a00.z); a00.w = fmaf(ew.x, w0.w, a00.w);
            a01.x = fmaf(ew.x, w1.x, a01.x); a01.y = fmaf(ew.x, w1.y, a01.y);
            a01.z = fmaf(ew.x, w1.z, a01.z); a01.w = fmaf(ew.x, w1.w, a01.w);
            a02.x = fmaf(ew.x, w2.x, a02.x); a02.y = fmaf(ew.x, w2.y, a02.y);
            a02.z = fmaf(ew.x, w2.z, a02.z); a02.w = fmaf(ew.x, w2.w, a02.w);
            a03.x = fmaf(ew.x, w3.x, a03.x); a03.y = fmaf(ew.x, w3.y, a03.y);
            a03.z = fmaf(ew.x, w3.z, a03.z); a03.w = fmaf(ew.x, w3.w, a03.w);

            a10.x = fmaf(ew.y, w0.x, a10.x); a10.y = fmaf(ew.y, w0.y, a10.y);
            a10.z = fmaf(ew.y, w0.z, a10.z); a10.w = fmaf(ew.y, w0.w, a10.w);
            a11.x = fmaf(ew.y, w1.x, a11.x); a11.y = fmaf(ew.y, w1.y, a11.y);
            a11.z = fmaf(ew.y, w1.z, a11.z); a11.w = fmaf(ew.y, w1.w, a11.w);
            a12.x = fmaf(ew.y, w2.x, a12.x); a12.y = fmaf(ew.y, w2.y, a12.y);
            a12.z = fmaf(ew.y, w2.z, a12.z); a12.w = fmaf(ew.y, w2.w, a12.w);
            a13.x = fmaf(ew.y, w3.x, a13.x); a13.y = fmaf(ew.y, w3.y, a13.y);
            a13.z = fmaf(ew.y, w3.z, a13.z); a13.w = fmaf(ew.y, w3.w, a13.w);

            a20.x = fmaf(ew.z, w0.x, a20.x); a20.y = fmaf(ew.z, w0.y, a20.y);
            a20.z = fmaf(ew.z, w0.z, a20.z); a20.w = fmaf(ew.z, w0.w, a20.w);
            a21.x = fmaf(ew.z, w1.x, a21.x); a21.y = fmaf(ew.z, w1.y, a21.y);
            a21.z = fmaf(ew.z, w1.z, a21.z); a21.w = fmaf(ew.z, w1.w, a21.w);
            a22.x = fmaf(ew.z, w2.x, a22.x); a22.y = fmaf(ew.z, w2.y, a22.y);
            a22.z = fmaf(ew.z, w2.z, a22.z); a22.w = fmaf(ew.z, w2.w, a22.w);
            a23.x = fmaf(ew.z, w3.x, a23.x); a23.y = fmaf(ew.z, w3.y, a23.y);
            a23.z = fmaf(ew.z, w3.z, a23.z); a23.w = fmaf(ew.z, w3.w, a23.w);

            a30.x = fmaf(ew.w, w0.x, a30.x); a30.y = fmaf(ew.w, w0.y, a30.y);
            a30.z = fmaf(ew.w, w0.z, a30.z); a30.w = fmaf(ew.w, w0.w, a30.w);
            a31.x = fmaf(ew.w, w1.x, a31.x); a31.y = fmaf(ew.w, w1.y, a31.y);
            a31.z = fmaf(ew.w, w1.z, a31.z); a31.w = fmaf(ew.w, w1.w, a31.w);
            a32.x = fmaf(ew.w, w2.x, a32.x); a32.y = fmaf(ew.w, w2.y, a32.y);
            a32.z = fmaf(ew.w, w2.z, a32.z); a32.w = fmaf(ew.w, w2.w, a32.w);
            a33.x = fmaf(ew.w, w3.x, a33.x); a33.y = fmaf(ew.w, w3.y, a33.y);
            a33.z = fmaf(ew.w, w3.z, a33.z); a33.w = fmaf(ew.w, w3.w, a33.w);
        }

        // epilogue: bias + silu + store
        float4 b0 = *(const float4*)(biasS + c0);
        float4 b1 = *(const float4*)(biasS + c0 + 128);
        float4 b2 = *(const float4*)(biasS + c0 + 256);
        float4 b3 = *(const float4*)(biasS + c0 + 384);

        float4 accs[4][4] = {{a00,a01,a02,a03},{a10,a11,a12,a13},
                             {a20,a21,a22,a23},{a30,a31,a32,a33}};
        float4 bs[4] = {b0,b1,b2,b3};
        #pragma unroll
        for (int e = 0; e < 4; e++) {
            float* out = d_ekv + (size_t)(e0 + g*4 + e)*512 + c0;
            #pragma unroll
            for (int p = 0; p < 4; p++) {
                float4 x = accs[e][p];
                x.x += bs[p].x; x.y += bs[p].y; x.z += bs[p].z; x.w += bs[p].w;
                float4 o;
                o.x = x.x / (1.f + __expf(-x.x));
                o.y = x.y / (1.f + __expf(-x.y));
                o.z = x.z / (1.f + __expf(-x.z));
                o.w = x.w / (1.f + __expf(-x.w));
                *(float4*)(out + p*128) = o;
            }
        }
    }
}

// ---------------- fused attention message kernel ----------------------------
__global__ void message_kernel(const float* __restrict__ v_in, float* __restrict__ v_out) {
    __shared__ float scut[KNN];
    __shared__ float svn[KNN*3];
    __shared__ float slog[KNN*NH];
    __shared__ float sattn[KNN*NH];
    __shared__ int   sj[KNN];

    int i = blockIdx.x, f = threadIdx.x;
    int w = f >> 5, lane = f & 31;          // warp = head (DH=32)

    if (f < KNN) { int e = i*KNN + f; sj[f] = d_idx[e]; scut[f] = d_cut[e]; }
    if (f < KNN*3) svn[f] = d_vecn[i*KNN*3 + f];
    __syncthreads();

    float q = d_qkv[i*640 + f];

    // pass 1: logits
    for (int k = 0; k < KNN; k++) {
        int j = sj[k];
        float p = q * d_qkv[j*640 + 128 + f] * d_ekv[(size_t)(i*KNN + k)*512 + f];
        #pragma unroll
        for (int off = 16; off; off >>= 1) p += __shfl_down_sync(0xffffffffu, p, off);
        if (lane == 0) slog[k*NH + w] = p * 0.125f;   // 1/sqrt(DH*TEMP) = 1/8
    }
    __syncthreads();

    // softmax over k per head, times cutoff
    {
        float lv = (lane < KNN) ? slog[lane*NH + w] : -1e30f;
        float mx = lv;
        #pragma unroll
        for (int off = 16; off; off >>= 1) mx = fmaxf(mx, __shfl_xor_sync(0xffffffffu, mx, off));
        float ex = (lane < KNN) ? expf(lv - mx) : 0.f;
        float sm = ex;
        #pragma unroll
        for (int off = 16; off; off >>= 1) sm += __shfl_xor_sync(0xffffffffu, sm, off);
        if (lane < KNN) sattn[lane*NH + w] = ex / sm * scut[lane];
    }
    __syncthreads();

    // pass 2: messages
    float ds = 0.f, dv0 = 0.f, dv1 = 0.f, dv2 = 0.f;
    for (int k = 0; k < KNN; k++) {
        int j  = sj[k];
        float wf = sattn[k*NH + w];
        size_t eb = (size_t)(i*KNN + k)*512;
        int jb = j*640;
        float m1 = d_qkv[jb + 256 + f] * d_ekv[eb + 128 + f];
        float m2 = d_qkv[jb + 384 + f] * d_ekv[eb + 256 + f];
        float m3 = d_qkv[jb + 512 + f] * d_ekv[eb + 384 + f];
        ds += wf * m1;
        float wm2 = wf * m2, wm3 = wf * m3;
        dv0 = fmaf(wm2, svn[k*3+0], fmaf(wm3, v_in[j*384 +        f], dv0));
        dv1 = fmaf(wm2, svn[k*3+1], fmaf(wm3, v_in[j*384 + 128 +  f], dv1));
        dv2 = fmaf(wm2, svn[k*3+2], fmaf(wm3, v_in[j*384 + 256 +  f], dv2));
    }
    d_s[i*FDIM + f] += ds;
    d_o[i*FDIM + f] += ds;
    v_out[i*384 +        f] = v_in[i*384 +        f] + dv0;
    v_out[i*384 + 128 +  f] = v_in[i*384 + 128 +  f] + dv1;
    v_out[i*384 + 256 +  f] = v_in[i*384 + 256 +  f] + dv2;
}

// ---------------- layernorm + readout ---------------------------------------
__global__ void readout_kernel(const float* __restrict__ ln_g, const float* __restrict__ ln_b,
                               const float* __restrict__ Wo1,  const float* __restrict__ Wo2) {
    __shared__ float red[128];
    __shared__ float son[128];
    int i = blockIdx.x, f = threadIdx.x;
    float x = d_o[i*FDIM + f];

    red[f] = x; __syncthreads();
    for (int s = 64; s > 0; s >>= 1) { if (f < s) red[f] += red[f+s]; __syncthreads(); }
    float mean = red[0] * (1.f/128.f);
    __syncthreads();

    float dx = x - mean;
    red[f] = dx*dx; __syncthreads();
    for (int s = 64; s > 0; s >>= 1) { if (f < s) red[f] += red[f+s]; __syncthreads(); }
    float var = red[0] * (1.f/128.f);
    __syncthreads();

    float on = dx * (1.f / sqrtf(var + 1e-5f)) * ln_g[f] + ln_b[f];
    son[f] = on; __syncthreads();

    float acc = 0.f;
    #pragma unroll 8
    for (int g = 0; g < 128; g++) acc = fmaf(son[g], Wo1[g*FDIM + f], acc);
    float tb = acc / (1.f + expf(-acc));     // silu
    red[f] = tb * Wo2[f];
    __syncthreads();
    for (int s = 64; s > 0; s >>= 1) { if (f < s) red[f] += red[f+s]; __syncthreads(); }
    if (f == 0) d_h[i] = red[0];
}

__global__ void sum_kernel(float* __restrict__ out) {
    __shared__ double rd[256];
    int t = threadIdx.x;
    double a = 0.0;
    for (int i = t; i < NA; i += 256) a += (double)d_h[i];
    rd[t] = a; __syncthreads();
    for (int s = 128; s > 0; s >>= 1) { if (t < s) rd[t] += rd[t+s]; __syncthreads(); }
    if (t == 0) out[0] = (float)rd[0];
}

// ---------------- launch ------------------------------------------------------
extern "C" void kernel_launch(void* const* d_in, const int* in_sizes, int n_in,
                              void* d_out, int out_size) {
    const int*   Z    = (const int*)  d_in[0];
    const float* R    = (const float*)d_in[1];
    const float* emb  = (const float*)d_in[3];
    const float* Wq   = (const float*)d_in[4];
    const float* Wk   = (const float*)d_in[5];
    const float* Wv   = (const float*)d_in[6];
    const float* We_k = (const float*)d_in[7];
    const float* be_k = (const float*)d_in[8];
    const float* We_v = (const float*)d_in[9];
    const float* be_v = (const float*)d_in[10];
    const float* ln_g = (const float*)d_in[11];
    const float* ln_b = (const float*)d_in[12];
    const float* Wo1  = (const float*)d_in[13];
    const float* Wo2  = (const float*)d_in[14];
    float* out = (float*)d_out;

    static float* v0p = nullptr;
    static float* v1p = nullptr;
    static bool attr_done = false;
    if (!v0p) {
        cudaGetSymbolAddress((void**)&v0p, d_v0);
        cudaGetSymbolAddress((void**)&v1p, d_v1);
    }
    if (!attr_done) {
        cudaFuncSetAttribute(ekv_kernel, cudaFuncAttributeMaxDynamicSharedMemorySize, EKV_SMEM);
        attr_done = true;
    }
    float* vbufs[2] = { v0p, v1p };

    init_kernel<<<(NA*3*FDIM + 255)/256, 256>>>(Z, emb);
    knn_kernel<<<NA, 256>>>(R);

    for (int l = 0; l < NL; l++) {
        qkv_gemm<<<dim3(NA/128, 10), 256>>>(Wq, Wk, Wv, l);
        ekv_kernel<<<NEDGE/EKV_EB, 256, EKV_SMEM>>>(We_k, be_k, We_v, be_v, l);
        message_kernel<<<NA, 128>>>(vbufs[l & 1], vbufs[(l + 1) & 1]);
    }

    readout_kernel<<<NA, 128>>>(ln_g, ln_b, Wo1, Wo2);
    sum_kernel<<<1, 256>>>(out);
}

// round 4
// speedup vs baseline: 1.4140x; 1.0954x over previous
#include <cuda_runtime.h>
#include <math.h>

#define NA   4096
#define FDIM 128
#define NH   4
#define DH   32
#define KNN  15
#define NKR  50
#define NL   6
#define NEDGE (NA*KNN)
#define WT   16            // RBF window taps

// ekv kernel tiling: block = 128 edges x 256 cols (half of 512)
#define EKV_EB    128      // edges per block
#define EKV_EPASS 32       // edges per pass (8 groups of 4)
#define EKV_NPASS (EKV_EB/EKV_EPASS)
#define EKV_NGRP  8        // warps per block == groups per pass
#define RPAD      50       // padded rows per group (exact: span <= 50 always)
#define HCOL      256      // cols per block half

// ---------------- scratch (static device globals; no runtime alloc) --------
__device__ float d_s[NA*FDIM];
__device__ float d_o[NA*FDIM];
__device__ float d_v0[NA*3*FDIM];
__device__ float d_v1[NA*3*FDIM];
__device__ float d_qkv[NA*640];            // [q(128) | k(128) | val(384)]
__device__ float d_ekv[NEDGE*512];         // [ek(128) | ev(384)] post-silu
__device__ float d_cut[NEDGE];
__device__ float d_dist[NEDGE];
__device__ float d_vecn[NEDGE*3];
__device__ int   d_idx[NEDGE];
__device__ float d_h[NA];

// ---------------- init: s = emb[Z], o = 0, v0 = 0 ---------------------------
__global__ void init_kernel(const int* __restrict__ Z, const float* __restrict__ emb) {
    int t = blockIdx.x * blockDim.x + threadIdx.x;
    if (t < NA*FDIM) {
        int i = t / FDIM, f = t % FDIM;
        d_s[t] = emb[Z[i]*FDIM + f];
        d_o[t] = 0.f;
    }
    if (t < NA*3*FDIM) d_v0[t] = 0.f;
}

// ---------------- KNN + edge geometry ---------------------------------------
__global__ void knn_kernel(const float* __restrict__ R) {
    __shared__ float sd2[NA];
    __shared__ float rv[256];
    __shared__ int   rj[256];
    __shared__ int   sidx[KNN];

    int i = blockIdx.x, t = threadIdx.x;
    float rx = R[i*3], ry = R[i*3+1], rz = R[i*3+2];
    float sqi = rx*rx + ry*ry + rz*rz;

    for (int j = t; j < NA; j += 256) {
        float x = R[j*3], y = R[j*3+1], z = R[j*3+2];
        float sqj = x*x + y*y + z*z;
        float dot = rx*x + ry*y + rz*z;
        float d2  = fmaxf(sqi + sqj - 2.f*dot, 0.f);
        if (j == i) d2 = 1e9f;
        sd2[j] = d2;
    }
    __syncthreads();

    for (int k = 0; k < KNN; k++) {
        float bv = 1e30f; int bj = 0x7fffffff;
        for (int j = t; j < NA; j += 256) {
            float v = sd2[j];
            if (v < bv) { bv = v; bj = j; }     // strict < keeps lowest index
        }
        rv[t] = bv; rj[t] = bj;
        __syncthreads();
        for (int s = 128; s > 0; s >>= 1) {
            if (t < s) {
                float v2 = rv[t+s]; int j2 = rj[t+s];
                if (v2 < rv[t] || (v2 == rv[t] && j2 < rj[t])) { rv[t] = v2; rj[t] = j2; }
            }
            __syncthreads();
        }
        if (t == 0) { sidx[k] = rj[0]; sd2[rj[0]] = 1e9f; }
        __syncthreads();
    }

    if (t < KNN) {
        int j = sidx[t];
        float vx = R[j*3]   - rx;
        float vy = R[j*3+1] - ry;
        float vz = R[j*3+2] - rz;
        float dd = sqrtf(vx*vx + vy*vy + vz*vz + 1e-12f);
        float inv = 1.f / dd;
        int e = i*KNN + t;
        d_idx[e] = j;
        d_vecn[e*3+0] = vx*inv;
        d_vecn[e*3+1] = vy*inv;
        d_vecn[e*3+2] = vz*inv;
        float c = (dd <= 5.f) ? 0.5f*(cosf(0.62831853071795864769f*dd) + 1.f) : 0.f;
        d_cut[e]  = c;
        d_dist[e] = dd;
    }
}

// ---------------- QKV GEMM: (4096x128)@(128x640), 128x64 tiles --------------
__global__ __launch_bounds__(256) void qkv_gemm(const float* __restrict__ Wq,
                                                const float* __restrict__ Wk,
                                                const float* __restrict__ Wv, int l) {
    __shared__ float As[8*128];   // [k][m]
    __shared__ float Bs[8*64];    // [k][n]
    int bm = blockIdx.x, bn = blockIdx.y, t = threadIdx.x;
    int m0 = bm * 128;
    int cb = bn * 64;
    const float* B; int ldb, coff;
    if (cb < 128)       { B = Wq + l*FDIM*FDIM; ldb = FDIM; coff = cb; }
    else if (cb < 256)  { B = Wk + l*FDIM*FDIM; ldb = FDIM; coff = cb - 128; }
    else                { B = Wv + l*FDIM*384;  ldb = 384;  coff = cb - 256; }

    int tx = t & 15;      // n: 4 cols
    int ty = t >> 4;      // m: 8 rows
    float acc[8][4] = {};

    for (int k0 = 0; k0 < 128; k0 += 8) {
        {
            int k = t & 7, mb = t >> 3;
            #pragma unroll
            for (int p = 0; p < 4; p++) {
                int m = mb + p*32;
                As[k*128 + m] = d_s[(m0 + m)*FDIM + k0 + k];
            }
            if (t < 128) {
                int kk = t >> 4, n4 = t & 15;
                *(float4*)&Bs[kk*64 + n4*4] =
                    *(const float4*)&B[(k0 + kk)*ldb + coff + n4*4];
            }
        }
        __syncthreads();
        #pragma unroll
        for (int kk = 0; kk < 8; kk++) {
            float a[8], b[4];
            #pragma unroll
            for (int x = 0; x < 8; x++) a[x] = As[kk*128 + ty*8 + x];
            #pragma unroll
            for (int x = 0; x < 4; x++) b[x] = Bs[kk*64 + tx*4 + x];
            #pragma unroll
            for (int ix = 0; ix < 8; ix++)
                #pragma unroll
                for (int jx = 0; jx < 4; jx++)
                    acc[ix][jx] = fmaf(a[ix], b[jx], acc[ix][jx]);
        }
        __syncthreads();
    }
    #pragma unroll
    for (int ix = 0; ix < 8; ix++) {
        float4 v = make_float4(acc[ix][0], acc[ix][1], acc[ix][2], acc[ix][3]);
        *(float4*)&d_qkv[(m0 + ty*8 + ix)*640 + cb + tx*4] = v;
    }
}

// ---------------- windowed edge filter + silu (column-split, padded taps) ---
// Block handles 128 edges x 256 of the 512 output cols (blockIdx.y = half).
// smem: Ws[50*256] | ewspad[NGRP*RPAD*4] | biasS[256] | small arrays
#define EKV_SM_WS    0
#define EKV_SM_EWS   (50*HCOL)
#define EKV_SM_BIAS  (EKV_SM_EWS + EKV_NGRP*RPAD*4)
#define EKV_SM_KBS   (EKV_SM_BIAS + HCOL)
#define EKV_SM_DDS   (EKV_SM_KBS + 32)
#define EKV_SM_CUTS  (EKV_SM_DDS + 32)
#define EKV_SM_RMIN  (EKV_SM_CUTS + 32)
#define EKV_SM_SPAN  (EKV_SM_RMIN + 8)
#define EKV_SMEM     ((EKV_SM_SPAN + 8) * 4)

__global__ __launch_bounds__(256, 3) void ekv_kernel(const float* __restrict__ Wek,
                                                     const float* __restrict__ bek,
                                                     const float* __restrict__ Wev,
                                                     const float* __restrict__ bev, int l) {
    extern __shared__ float sm[];
    float* Ws    = sm + EKV_SM_WS;
    float* ews   = sm + EKV_SM_EWS;
    float* biasS = sm + EKV_SM_BIAS;
    int*   kbs   = (int*)(sm + EKV_SM_KBS);
    float* dds   = sm + EKV_SM_DDS;
    float* cuts  = sm + EKV_SM_CUTS;
    int*   rminS = (int*)(sm + EKV_SM_RMIN);
    int*   spanS = (int*)(sm + EKV_SM_SPAN);

    int tid  = threadIdx.x;
    int lane = tid & 31;
    int g    = tid >> 5;                    // warp == group
    int eblk = blockIdx.x * EKV_EB;
    int h    = blockIdx.y;                  // column half: 0 -> cols 0..255, 1 -> 256..511

    // load this half's weight cols [h*256, h*256+256) of [We_k(128)|We_v(384)]
    {
        float4* Ws4 = (float4*)Ws;
        const float4* Wek4 = (const float4*)(Wek + l*50*FDIM);
        const float4* Wev4 = (const float4*)(Wev + l*50*384);
        int hb = h * 64;
        for (int q = tid; q < 50*64; q += 256) {
            int row = q >> 6;
            int gc4 = hb + (q & 63);
            Ws4[q] = (gc4 < 32) ? Wek4[row*32 + gc4] : Wev4[row*96 + (gc4 - 32)];
        }
        if (tid < 64) {
            int gb4 = hb + tid;
            float4 b = (gb4 < 32) ? ((const float4*)(bek + l*FDIM))[gb4]
                                  : ((const float4*)(bev + l*384))[gb4 - 32];
            ((float4*)biasS)[tid] = b;
        }
    }

    int c0 = lane * 4;

    for (int pass = 0; pass < EKV_NPASS; pass++) {
        int e0 = eblk + pass * EKV_EPASS;
        __syncthreads();                    // Ws/bias ready; prev compute done

        // zero tap pad
        {
            float4 z = make_float4(0.f, 0.f, 0.f, 0.f);
            for (int u = tid; u < EKV_NGRP*RPAD; u += 256)
                ((float4*)ews)[u] = z;
        }
        // per-edge window base
        if (tid < EKV_EPASS) {
            int ge = e0 + tid;
            float dd = d_dist[ge];
            float fi = dd * (49.0f/5.0f);
            int k0 = (int)floorf(fi + 0.5f) - 7;
            k0 = max(0, min(50 - WT, k0));
            kbs[tid]  = k0;
            dds[tid]  = dd;
            cuts[tid] = d_cut[ge];
        }
        __syncthreads();
        if (tid < EKV_NGRP) {
            int a0 = kbs[tid*4], a1 = kbs[tid*4+1], a2 = kbs[tid*4+2], a3 = kbs[tid*4+3];
            int rmin = min(min(a0,a1), min(a2,a3));
            int rmax = max(max(a0,a1), max(a2,a3)) + WT;
            rminS[tid] = rmin;
            spanS[tid] = rmax - rmin;
        }
        __syncthreads();
        // scatter 16 taps per edge into padded array
        for (int u = tid; u < EKV_EPASS*WT; u += 256) {
            int e = u >> 4, tt = u & 15;
            int gg = e >> 2;
            int kk = kbs[e];
            int row = kk + tt - rminS[gg];
            float mu = (float)(kk + tt) * (5.0f/49.0f);
            float df = dds[e] - mu;
            ews[(gg*RPAD + row)*4 + (e & 3)] = __expf(-df*df*50.0f) * cuts[e];
        }
        __syncthreads();

        // compute: warp g -> its 4 edges; thread -> cols c0 and c0+128 of this half
        int rmin = rminS[g];
        int span = spanS[g];
        const float* wp = Ws + rmin*HCOL + c0;
        const float4* ep = (const float4*)(ews + g*RPAD*4);

        float4 a00 = make_float4(0,0,0,0), a01 = a00;
        float4 a10 = a00, a11 = a00;
        float4 a20 = a00, a21 = a00;
        float4 a30 = a00, a31 = a00;

        for (int r = 0; r < span; r++) {
            float4 ew = ep[r];
            float4 w0 = *(const float4*)(wp);
            float4 w1 = *(const float4*)(wp + 128);
            wp += HCOL;
            a00.x = fmaf(ew.x, w0.x, a00.x); a00.y = fmaf(ew.x, w0.y, a00.y);
            a00.z = fmaf(ew.x, w0.z, a00.z); a00.w = fmaf(ew.x, w0.w, a00.w);
            a01.x = fmaf(ew.x, w1.x, a01.x); a01.y = fmaf(ew.x, w1.y, a01.y);
            a01.z = fmaf(ew.x, w1.z, a01.z); a01.w = fmaf(ew.x, w1.w, a01.w);

            a10.x = fmaf(ew.y, w0.x, a10.x); a10.y = fmaf(ew.y, w0.y, a10.y);
            a10.z = fmaf(ew.y, w0.z, a10.z); a10.w = fmaf(ew.y, w0.w, a10.w);
            a11.x = fmaf(ew.y, w1.x, a11.x); a11.y = fmaf(ew.y, w1.y, a11.y);
            a11.z = fmaf(ew.y, w1.z, a11.z); a11.w = fmaf(ew.y, w1.w, a11.w);

            a20.x = fmaf(ew.z, w0.x, a20.x); a20.y = fmaf(ew.z, w0.y, a20.y);
            a20.z = fmaf(ew.z, w0.z, a20.z); a20.w = fmaf(ew.z, w0.w, a20.w);
            a21.x = fmaf(ew.z, w1.x, a21.x); a21.y = fmaf(ew.z, w1.y, a21.y);
            a21.z = fmaf(ew.z, w1.z, a21.z); a21.w = fmaf(ew.z, w1.w, a21.w);

            a30.x = fmaf(ew.w, w0.x, a30.x); a30.y = fmaf(ew.w, w0.y, a30.y);
            a30.z = fmaf(ew.w, w0.z, a30.z); a30.w = fmaf(ew.w, w0.w, a30.w);
            a31.x = fmaf(ew.w, w1.x, a31.x); a31.y = fmaf(ew.w, w1.y, a31.y);
            a31.z = fmaf(ew.w, w1.z, a31.z); a31.w = fmaf(ew.w, w1.w, a31.w);
        }

        // epilogue: bias + silu + store to global cols h*256 + {c0, c0+128}
        float4 b0 = *(const float4*)(biasS + c0);
        float4 b1 = *(const float4*)(biasS + c0 + 128);
        float4 accs[4][2] = {{a00,a01},{a10,a11},{a20,a21},{a30,a31}};
        float4 bs[2] = {b0,b1};
        int gcol = h * HCOL + c0;
        #pragma unroll
        for (int e = 0; e < 4; e++) {
            float* out = d_ekv + (size_t)(e0 + g*4 + e)*512 + gcol;
            #pragma unroll
            for (int p = 0; p < 2; p++) {
                float4 x = accs[e][p];
                x.x += bs[p].x; x.y += bs[p].y; x.z += bs[p].z; x.w += bs[p].w;
                float4 o;
                o.x = x.x / (1.f + __expf(-x.x));
                o.y = x.y / (1.f + __expf(-x.y));
                o.z = x.z / (1.f + __expf(-x.z));
                o.w = x.w / (1.f + __expf(-x.w));
                *(float4*)(out + p*128) = o;
            }
        }
    }
}

// ---------------- fused attention message kernel ----------------------------
__global__ void message_kernel(const float* __restrict__ v_in, float* __restrict__ v_out) {
    __shared__ float scut[KNN];
    __shared__ float svn[KNN*3];
    __shared__ float slog[KNN*NH];
    __shared__ float sattn[KNN*NH];
    __shared__ int   sj[KNN];

    int i = blockIdx.x, f = threadIdx.x;
    int w = f >> 5, lane = f & 31;          // warp = head (DH=32)

    if (f < KNN) { int e = i*KNN + f; sj[f] = d_idx[e]; scut[f] = d_cut[e]; }
    if (f < KNN*3) svn[f] = d_vecn[i*KNN*3 + f];
    __syncthreads();

    float q = d_qkv[i*640 + f];

    // pass 1: logits
    #pragma unroll
    for (int k = 0; k < KNN; k++) {
        int j = sj[k];
        float p = q * d_qkv[j*640 + 128 + f] * d_ekv[(size_t)(i*KNN + k)*512 + f];
        #pragma unroll
        for (int off = 16; off; off >>= 1) p += __shfl_down_sync(0xffffffffu, p, off);
        if (lane == 0) slog[k*NH + w] = p * 0.125f;   // 1/sqrt(DH*TEMP) = 1/8
    }
    __syncthreads();

    // softmax over k per head, times cutoff
    {
        float lv = (lane < KNN) ? slog[lane*NH + w] : -1e30f;
        float mx = lv;
        #pragma unroll
        for (int off = 16; off; off >>= 1) mx = fmaxf(mx, __shfl_xor_sync(0xffffffffu, mx, off));
        float ex = (lane < KNN) ? expf(lv - mx) : 0.f;
        float sm = ex;
        #pragma unroll
        for (int off = 16; off; off >>= 1) sm += __shfl_xor_sync(0xffffffffu, sm, off);
        if (lane < KNN) sattn[lane*NH + w] = ex / sm * scut[lane];
    }
    __syncthreads();

    // pass 2: messages
    float ds = 0.f, dv0 = 0.f, dv1 = 0.f, dv2 = 0.f;
    #pragma unroll 5
    for (int k = 0; k < KNN; k++) {
        int j  = sj[k];
        float wf = sattn[k*NH + w];
        size_t eb = (size_t)(i*KNN + k)*512;
        int jb = j*640;
        float m1 = d_qkv[jb + 256 + f] * d_ekv[eb + 128 + f];
        float m2 = d_qkv[jb + 384 + f] * d_ekv[eb + 256 + f];
        float m3 = d_qkv[jb + 512 + f] * d_ekv[eb + 384 + f];
        ds += wf * m1;
        float wm2 = wf * m2, wm3 = wf * m3;
        dv0 = fmaf(wm2, svn[k*3+0], fmaf(wm3, v_in[j*384 +        f], dv0));
        dv1 = fmaf(wm2, svn[k*3+1], fmaf(wm3, v_in[j*384 + 128 +  f], dv1));
        dv2 = fmaf(wm2, svn[k*3+2], fmaf(wm3, v_in[j*384 + 256 +  f], dv2));
    }
    d_s[i*FDIM + f] += ds;
    d_o[i*FDIM + f] += ds;
    v_out[i*384 +        f] = v_in[i*384 +        f] + dv0;
    v_out[i*384 + 128 +  f] = v_in[i*384 + 128 +  f] + dv1;
    v_out[i*384 + 256 +  f] = v_in[i*384 + 256 +  f] + dv2;
}

// ---------------- layernorm + readout ---------------------------------------
__global__ void readout_kernel(const float* __restrict__ ln_g, const float* __restrict__ ln_b,
                               const float* __restrict__ Wo1,  const float* __restrict__ Wo2) {
    __shared__ float red[128];
    __shared__ float son[128];
    int i = blockIdx.x, f = threadIdx.x;
    float x = d_o[i*FDIM + f];

    red[f] = x; __syncthreads();
    for (int s = 64; s > 0; s >>= 1) { if (f < s) red[f] += red[f+s]; __syncthreads(); }
    float mean = red[0] * (1.f/128.f);
    __syncthreads();

    float dx = x - mean;
    red[f] = dx*dx; __syncthreads();
    for (int s = 64; s > 0; s >>= 1) { if (f < s) red[f] += red[f+s]; __syncthreads(); }
    float var = red[0] * (1.f/128.f);
    __syncthreads();

    float on = dx * (1.f / sqrtf(var + 1e-5f)) * ln_g[f] + ln_b[f];
    son[f] = on; __syncthreads();

    float acc = 0.f;
    #pragma unroll 8
    for (int g = 0; g < 128; g++) acc = fmaf(son[g], Wo1[g*FDIM + f], acc);
    float tb = acc / (1.f + expf(-acc));     // silu
    red[f] = tb * Wo2[f];
    __syncthreads();
    for (int s = 64; s > 0; s >>= 1) { if (f < s) red[f] += red[f+s]; __syncthreads(); }
    if (f == 0) d_h[i] = red[0];
}

__global__ void sum_kernel(float* __restrict__ out) {
    __shared__ double rd[256];
    int t = threadIdx.x;
    double a = 0.0;
    for (int i = t; i < NA; i += 256) a += (double)d_h[i];
    rd[t] = a; __syncthreads();
    for (int s = 128; s > 0; s >>= 1) { if (t < s) rd[t] += rd[t+s]; __syncthreads(); }
    if (t == 0) out[0] = (float)rd[0];
}

// ---------------- launch ------------------------------------------------------
extern "C" void kernel_launch(void* const* d_in, const int* in_sizes, int n_in,
                              void* d_out, int out_size) {
    const int*   Z    = (const int*)  d_in[0];
    const float* R    = (const float*)d_in[1];
    const float* emb  = (const float*)d_in[3];
    const float* Wq   = (const float*)d_in[4];
    const float* Wk   = (const float*)d_in[5];
    const float* Wv   = (const float*)d_in[6];
    const float* We_k = (const float*)d_in[7];
    const float* be_k = (const float*)d_in[8];
    const float* We_v = (const float*)d_in[9];
    const float* be_v = (const float*)d_in[10];
    const float* ln_g = (const float*)d_in[11];
    const float* ln_b = (const float*)d_in[12];
    const float* Wo1  = (const float*)d_in[13];
    const float* Wo2  = (const float*)d_in[14];
    float* out = (float*)d_out;

    static float* v0p = nullptr;
    static float* v1p = nullptr;
    static cudaStream_t s1 = nullptr;
    static cudaEvent_t evA = nullptr, evB = nullptr;
    if (!v0p) {
        cudaGetSymbolAddress((void**)&v0p, d_v0);
        cudaGetSymbolAddress((void**)&v1p, d_v1);
        cudaFuncSetAttribute(ekv_kernel, cudaFuncAttributeMaxDynamicSharedMemorySize, EKV_SMEM);
        cudaStreamCreateWithFlags(&s1, cudaStreamNonBlocking);
        cudaEventCreateWithFlags(&evA, cudaEventDisableTiming);
        cudaEventCreateWithFlags(&evB, cudaEventDisableTiming);
    }
    float* vbufs[2] = { v0p, v1p };

    init_kernel<<<(NA*3*FDIM + 255)/256, 256>>>(Z, emb);
    knn_kernel<<<NA, 256>>>(R);

    for (int l = 0; l < NL; l++) {
        // fork: qkv on s1 (depends on d_s from prev message / init)
        cudaEventRecord(evA, 0);
        cudaStreamWaitEvent(s1, evA, 0);
        qkv_gemm<<<dim3(NA/128, 10), 256, 0, s1>>>(Wq, Wk, Wv, l);
        cudaEventRecord(evB, s1);
        // ekv on default stream (independent of qkv)
        ekv_kernel<<<dim3(NEDGE/EKV_EB, 2), 256, EKV_SMEM>>>(We_k, be_k, We_v, be_v, l);
        // join: message needs both
        cudaStreamWaitEvent(0, evB, 0);
        message_kernel<<<NA, 128>>>(vbufs[l & 1], vbufs[(l + 1) & 1]);
    }

    readout_kernel<<<NA, 128>>>(ln_g, ln_b, Wo1, Wo2);
    sum_kernel<<<1, 256>>>(out);
}

// round 5
// speedup vs baseline: 1.6715x; 1.1821x over previous
#include <cuda_runtime.h>
#include <cuda_fp16.h>
#include <math.h>

#define NA   4096
#define FDIM 128
#define NH   4
#define DH   32
#define KNN  15
#define NKR  50
#define NL   6
#define NEDGE (NA*KNN)
#define WT   16            // RBF window taps

// ekv kernel tiling: block = 128 edges x 256 cols (half of 512)
#define EKV_EB    128
#define EKV_EPASS 32       // edges per pass (8 groups of 4)
#define EKV_NPASS (EKV_EB/EKV_EPASS)
#define EKV_NGRP  8
#define RPAD      50
#define HCOL      256

// ---------------- scratch (static device globals; no runtime alloc) --------
__device__ float d_s[NA*FDIM];
__device__ float d_o[NA*FDIM];
__device__ float d_v0[NA*3*FDIM];
__device__ float d_v1[NA*3*FDIM];
__device__ float d_qkv[NA*640];            // [q(128) | k(128) | val(384)]
__device__ __half d_ekvh0[NEDGE*512];      // fp16 [ek(128)|ev(384)] ping
__device__ __half d_ekvh1[NEDGE*512];      // fp16 pong
__device__ float d_cut[NEDGE];
__device__ float d_dist[NEDGE];
__device__ float d_vecn[NEDGE*3];
__device__ int   d_idx[NEDGE];
__device__ float d_h[NA];

// ---------------- init ------------------------------------------------------
__global__ void init_kernel(const int* __restrict__ Z, const float* __restrict__ emb) {
    int t = blockIdx.x * blockDim.x + threadIdx.x;
    if (t < NA*FDIM) {
        int i = t / FDIM, f = t % FDIM;
        d_s[t] = emb[Z[i]*FDIM + f];
        d_o[t] = 0.f;
    }
    if (t < NA*3*FDIM) d_v0[t] = 0.f;
}

// ---------------- KNN + edge geometry ---------------------------------------
__global__ void knn_kernel(const float* __restrict__ R) {
    __shared__ float sd2[NA];
    __shared__ float rv[256];
    __shared__ int   rj[256];
    __shared__ int   sidx[KNN];

    int i = blockIdx.x, t = threadIdx.x;
    float rx = R[i*3], ry = R[i*3+1], rz = R[i*3+2];
    float sqi = rx*rx + ry*ry + rz*rz;

    for (int j = t; j < NA; j += 256) {
        float x = R[j*3], y = R[j*3+1], z = R[j*3+2];
        float sqj = x*x + y*y + z*z;
        float dot = rx*x + ry*y + rz*z;
        float d2  = fmaxf(sqi + sqj - 2.f*dot, 0.f);
        if (j == i) d2 = 1e9f;
        sd2[j] = d2;
    }
    __syncthreads();

    for (int k = 0; k < KNN; k++) {
        float bv = 1e30f; int bj = 0x7fffffff;
        for (int j = t; j < NA; j += 256) {
            float v = sd2[j];
            if (v < bv) { bv = v; bj = j; }
        }
        rv[t] = bv; rj[t] = bj;
        __syncthreads();
        for (int s = 128; s > 0; s >>= 1) {
            if (t < s) {
                float v2 = rv[t+s]; int j2 = rj[t+s];
                if (v2 < rv[t] || (v2 == rv[t] && j2 < rj[t])) { rv[t] = v2; rj[t] = j2; }
            }
            __syncthreads();
        }
        if (t == 0) { sidx[k] = rj[0]; sd2[rj[0]] = 1e9f; }
        __syncthreads();
    }

    if (t < KNN) {
        int j = sidx[t];
        float vx = R[j*3]   - rx;
        float vy = R[j*3+1] - ry;
        float vz = R[j*3+2] - rz;
        float dd = sqrtf(vx*vx + vy*vy + vz*vz + 1e-12f);
        float inv = 1.f / dd;
        int e = i*KNN + t;
        d_idx[e] = j;
        d_vecn[e*3+0] = vx*inv;
        d_vecn[e*3+1] = vy*inv;
        d_vecn[e*3+2] = vz*inv;
        float c = (dd <= 5.f) ? 0.5f*(cosf(0.62831853071795864769f*dd) + 1.f) : 0.f;
        d_cut[e]  = c;
        d_dist[e] = dd;
    }
}

// ---------------- QKV GEMM: (4096x128)@(128x640), 128x64 tiles --------------
__global__ __launch_bounds__(256) void qkv_gemm(const float* __restrict__ Wq,
                                                const float* __restrict__ Wk,
                                                const float* __restrict__ Wv, int l) {
    __shared__ float As[8*128];
    __shared__ float Bs[8*64];
    int bm = blockIdx.x, bn = blockIdx.y, t = threadIdx.x;
    int m0 = bm * 128;
    int cb = bn * 64;
    const float* B; int ldb, coff;
    if (cb < 128)       { B = Wq + l*FDIM*FDIM; ldb = FDIM; coff = cb; }
    else if (cb < 256)  { B = Wk + l*FDIM*FDIM; ldb = FDIM; coff = cb - 128; }
    else                { B = Wv + l*FDIM*384;  ldb = 384;  coff = cb - 256; }

    int tx = t & 15;
    int ty = t >> 4;
    float acc[8][4] = {};

    for (int k0 = 0; k0 < 128; k0 += 8) {
        {
            int k = t & 7, mb = t >> 3;
            #pragma unroll
            for (int p = 0; p < 4; p++) {
                int m = mb + p*32;
                As[k*128 + m] = d_s[(m0 + m)*FDIM + k0 + k];
            }
            if (t < 128) {
                int kk = t >> 4, n4 = t & 15;
                *(float4*)&Bs[kk*64 + n4*4] =
                    *(const float4*)&B[(k0 + kk)*ldb + coff + n4*4];
            }
        }
        __syncthreads();
        #pragma unroll
        for (int kk = 0; kk < 8; kk++) {
            float a[8], b[4];
            #pragma unroll
            for (int x = 0; x < 8; x++) a[x] = As[kk*128 + ty*8 + x];
            #pragma unroll
            for (int x = 0; x < 4; x++) b[x] = Bs[kk*64 + tx*4 + x];
            #pragma unroll
            for (int ix = 0; ix < 8; ix++)
                #pragma unroll
                for (int jx = 0; jx < 4; jx++)
                    acc[ix][jx] = fmaf(a[ix], b[jx], acc[ix][jx]);
        }
        __syncthreads();
    }
    #pragma unroll
    for (int ix = 0; ix < 8; ix++) {
        float4 v = make_float4(acc[ix][0], acc[ix][1], acc[ix][2], acc[ix][3]);
        *(float4*)&d_qkv[(m0 + ty*8 + ix)*640 + cb + tx*4] = v;
    }
}

// ---------------- windowed edge filter + silu -> fp16 ------------------------
#define EKV_SM_WS    0
#define EKV_SM_EWS   (50*HCOL)
#define EKV_SM_BIAS  (EKV_SM_EWS + EKV_NGRP*RPAD*4)
#define EKV_SM_KBS   (EKV_SM_BIAS + HCOL)
#define EKV_SM_DDS   (EKV_SM_KBS + 32)
#define EKV_SM_CUTS  (EKV_SM_DDS + 32)
#define EKV_SM_RMIN  (EKV_SM_CUTS + 32)
#define EKV_SM_SPAN  (EKV_SM_RMIN + 8)
#define EKV_SMEM     ((EKV_SM_SPAN + 8) * 4)

__global__ __launch_bounds__(256, 3) void ekv_kernel(const float* __restrict__ Wek,
                                                     const float* __restrict__ bek,
                                                     const float* __restrict__ Wev,
                                                     const float* __restrict__ bev,
                                                     int l, __half* __restrict__ ekv_out) {
    extern __shared__ float sm[];
    float* Ws    = sm + EKV_SM_WS;
    float* ews   = sm + EKV_SM_EWS;
    float* biasS = sm + EKV_SM_BIAS;
    int*   kbs   = (int*)(sm + EKV_SM_KBS);
    float* dds   = sm + EKV_SM_DDS;
    float* cuts  = sm + EKV_SM_CUTS;
    int*   rminS = (int*)(sm + EKV_SM_RMIN);
    int*   spanS = (int*)(sm + EKV_SM_SPAN);

    int tid  = threadIdx.x;
    int lane = tid & 31;
    int g    = tid >> 5;
    int eblk = blockIdx.x * EKV_EB;
    int h    = blockIdx.y;

    {
        float4* Ws4 = (float4*)Ws;
        const float4* Wek4 = (const float4*)(Wek + l*50*FDIM);
        const float4* Wev4 = (const float4*)(Wev + l*50*384);
        int hb = h * 64;
        for (int q = tid; q < 50*64; q += 256) {
            int row = q >> 6;
            int gc4 = hb + (q & 63);
            Ws4[q] = (gc4 < 32) ? Wek4[row*32 + gc4] : Wev4[row*96 + (gc4 - 32)];
        }
        if (tid < 64) {
            int gb4 = hb + tid;
            float4 b = (gb4 < 32) ? ((const float4*)(bek + l*FDIM))[gb4]
                                  : ((const float4*)(bev + l*384))[gb4 - 32];
            ((float4*)biasS)[tid] = b;
        }
    }

    int c0 = lane * 4;

    for (int pass = 0; pass < EKV_NPASS; pass++) {
        int e0 = eblk + pass * EKV_EPASS;
        __syncthreads();

        {
            float4 z = make_float4(0.f, 0.f, 0.f, 0.f);
            for (int u = tid; u < EKV_NGRP*RPAD; u += 256)
                ((float4*)ews)[u] = z;
        }
        if (tid < EKV_EPASS) {
            int ge = e0 + tid;
            float dd = d_dist[ge];
            float fi = dd * (49.0f/5.0f);
            int k0 = (int)floorf(fi + 0.5f) - 7;
            k0 = max(0, min(50 - WT, k0));
            kbs[tid]  = k0;
            dds[tid]  = dd;
            cuts[tid] = d_cut[ge];
        }
        __syncthreads();
        if (tid < EKV_NGRP) {
            int a0 = kbs[tid*4], a1 = kbs[tid*4+1], a2 = kbs[tid*4+2], a3 = kbs[tid*4+3];
            int rmin = min(min(a0,a1), min(a2,a3));
            int rmax = max(max(a0,a1), max(a2,a3)) + WT;
            rminS[tid] = rmin;
            spanS[tid] = rmax - rmin;
        }
        __syncthreads();
        for (int u = tid; u < EKV_EPASS*WT; u += 256) {
            int e = u >> 4, tt = u & 15;
            int gg = e >> 2;
            int kk = kbs[e];
            int row = kk + tt - rminS[gg];
            float mu = (float)(kk + tt) * (5.0f/49.0f);
            float df = dds[e] - mu;
            ews[(gg*RPAD + row)*4 + (e & 3)] = __expf(-df*df*50.0f) * cuts[e];
        }
        __syncthreads();

        int rmin = rminS[g];
        int span = spanS[g];
        const float* wp = Ws + rmin*HCOL + c0;
        const float4* ep = (const float4*)(ews + g*RPAD*4);

        float4 a00 = make_float4(0,0,0,0), a01 = a00;
        float4 a10 = a00, a11 = a00;
        float4 a20 = a00, a21 = a00;
        float4 a30 = a00, a31 = a00;

        for (int r = 0; r < span; r++) {
            float4 ew = ep[r];
            float4 w0 = *(const float4*)(wp);
            float4 w1 = *(const float4*)(wp + 128);
            wp += HCOL;
            a00.x = fmaf(ew.x, w0.x, a00.x); a00.y = fmaf(ew.x, w0.y, a00.y);
            a00.z = fmaf(ew.x, w0.z, a00.z); a00.w = fmaf(ew.x, w0.w, a00.w);
            a01.x = fmaf(ew.x, w1.x, a01.x); a01.y = fmaf(ew.x, w1.y, a01.y);
            a01.z = fmaf(ew.x, w1.z, a01.z); a01.w = fmaf(ew.x, w1.w, a01.w);

            a10.x = fmaf(ew.y, w0.x, a10.x); a10.y = fmaf(ew.y, w0.y, a10.y);
            a10.z = fmaf(ew.y, w0.z, a10.z); a10.w = fmaf(ew.y, w0.w, a10.w);
            a11.x = fmaf(ew.y, w1.x, a11.x); a11.y = fmaf(ew.y, w1.y, a11.y);
            a11.z = fmaf(ew.y, w1.z, a11.z); a11.w = fmaf(ew.y, w1.w, a11.w);

            a20.x = fmaf(ew.z, w0.x, a20.x); a20.y = fmaf(ew.z, w0.y, a20.y);
            a20.z = fmaf(ew.z, w0.z, a20.z); a20.w = fmaf(ew.z, w0.w, a20.w);
            a21.x = fmaf(ew.z, w1.x, a21.x); a21.y = fmaf(ew.z, w1.y, a21.y);
            a21.z = fmaf(ew.z, w1.z, a21.z); a21.w = fmaf(ew.z, w1.w, a21.w);

            a30.x = fmaf(ew.w, w0.x, a30.x); a30.y = fmaf(ew.w, w0.y, a30.y);
            a30.z = fmaf(ew.w, w0.z, a30.z); a30.w = fmaf(ew.w, w0.w, a30.w);
            a31.x = fmaf(ew.w, w1.x, a31.x); a31.y = fmaf(ew.w, w1.y, a31.y);
            a31.z = fmaf(ew.w, w1.z, a31.z); a31.w = fmaf(ew.w, w1.w, a31.w);
        }

        float4 b0 = *(const float4*)(biasS + c0);
        float4 b1 = *(const float4*)(biasS + c0 + 128);
        float4 accs[4][2] = {{a00,a01},{a10,a11},{a20,a21},{a30,a31}};
        float4 bs[2] = {b0,b1};
        int gcol = h * HCOL + c0;
        #pragma unroll
        for (int e = 0; e < 4; e++) {
            __half* out = ekv_out + (size_t)(e0 + g*4 + e)*512 + gcol;
            #pragma unroll
            for (int p = 0; p < 2; p++) {
                float4 x = accs[e][p];
                x.x += bs[p].x; x.y += bs[p].y; x.z += bs[p].z; x.w += bs[p].w;
                float s0 = x.x / (1.f + __expf(-x.x));
                float s1 = x.y / (1.f + __expf(-x.y));
                float s2 = x.z / (1.f + __expf(-x.z));
                float s3 = x.w / (1.f + __expf(-x.w));
                __half2 h0 = __floats2half2_rn(s0, s1);
                __half2 h1 = __floats2half2_rn(s2, s3);
                *(__half2*)(out + p*128)     = h0;
                *(__half2*)(out + p*128 + 2) = h1;
            }
        }
    }
}

// ---------------- fused attention message kernel ----------------------------
__global__ void message_kernel(const float* __restrict__ v_in, float* __restrict__ v_out,
                               const __half* __restrict__ ekv) {
    __shared__ float scut[KNN];
    __shared__ float svn[KNN*3];
    __shared__ float slog[KNN*NH];
    __shared__ float sattn[KNN*NH];
    __shared__ int   sj[KNN];

    int i = blockIdx.x, f = threadIdx.x;
    int w = f >> 5, lane = f & 31;

    if (f < KNN) { int e = i*KNN + f; sj[f] = d_idx[e]; scut[f] = d_cut[e]; }
    if (f < KNN*3) svn[f] = d_vecn[i*KNN*3 + f];
    __syncthreads();

    float q = d_qkv[i*640 + f];

    #pragma unroll 3
    for (int k = 0; k < KNN; k++) {
        int j = sj[k];
        float ekf = __half2float(ekv[(size_t)(i*KNN + k)*512 + f]);
        float p = q * d_qkv[j*640 + 128 + f] * ekf;
        #pragma unroll
        for (int off = 16; off; off >>= 1) p += __shfl_down_sync(0xffffffffu, p, off);
        if (lane == 0) slog[k*NH + w] = p * 0.125f;
    }
    __syncthreads();

    {
        float lv = (lane < KNN) ? slog[lane*NH + w] : -1e30f;
        float mx = lv;
        #pragma unroll
        for (int off = 16; off; off >>= 1) mx = fmaxf(mx, __shfl_xor_sync(0xffffffffu, mx, off));
        float ex = (lane < KNN) ? expf(lv - mx) : 0.f;
        float sm = ex;
        #pragma unroll
        for (int off = 16; off; off >>= 1) sm += __shfl_xor_sync(0xffffffffu, sm, off);
        if (lane < KNN) sattn[lane*NH + w] = ex / sm * scut[lane];
    }
    __syncthreads();

    float ds = 0.f, dv0 = 0.f, dv1 = 0.f, dv2 = 0.f;
    #pragma unroll 3
    for (int k = 0; k < KNN; k++) {
        int j  = sj[k];
        float wf = sattn[k*NH + w];
        size_t eb = (size_t)(i*KNN + k)*512;
        int jb = j*640;
        float e1 = __half2float(ekv[eb + 128 + f]);
        float e2 = __half2float(ekv[eb + 256 + f]);
        float e3 = __half2float(ekv[eb + 384 + f]);
        float m1 = d_qkv[jb + 256 + f] * e1;
        float m2 = d_qkv[jb + 384 + f] * e2;
        float m3 = d_qkv[jb + 512 + f] * e3;
        ds += wf * m1;
        float wm2 = wf * m2, wm3 = wf * m3;
        dv0 = fmaf(wm2, svn[k*3+0], fmaf(wm3, v_in[j*384 +        f], dv0));
        dv1 = fmaf(wm2, svn[k*3+1], fmaf(wm3, v_in[j*384 + 128 +  f], dv1));
        dv2 = fmaf(wm2, svn[k*3+2], fmaf(wm3, v_in[j*384 + 256 +  f], dv2));
    }
    d_s[i*FDIM + f] += ds;
    d_o[i*FDIM + f] += ds;
    v_out[i*384 +        f] = v_in[i*384 +        f] + dv0;
    v_out[i*384 + 128 +  f] = v_in[i*384 + 128 +  f] + dv1;
    v_out[i*384 + 256 +  f] = v_in[i*384 + 256 +  f] + dv2;
}

// ---------------- layernorm + readout ---------------------------------------
__global__ void readout_kernel(const float* __restrict__ ln_g, const float* __restrict__ ln_b,
                               const float* __restrict__ Wo1,  const float* __restrict__ Wo2) {
    __shared__ float red[128];
    __shared__ float son[128];
    int i = blockIdx.x, f = threadIdx.x;
    float x = d_o[i*FDIM + f];

    red[f] = x; __syncthreads();
    for (int s = 64; s > 0; s >>= 1) { if (f < s) red[f] += red[f+s]; __syncthreads(); }
    float mean = red[0] * (1.f/128.f);
    __syncthreads();

    float dx = x - mean;
    red[f] = dx*dx; __syncthreads();
    for (int s = 64; s > 0; s >>= 1) { if (f < s) red[f] += red[f+s]; __syncthreads(); }
    float var = red[0] * (1.f/128.f);
    __syncthreads();

    float on = dx * (1.f / sqrtf(var + 1e-5f)) * ln_g[f] + ln_b[f];
    son[f] = on; __syncthreads();

    float acc = 0.f;
    #pragma unroll 8
    for (int g = 0; g < 128; g++) acc = fmaf(son[g], Wo1[g*FDIM + f], acc);
    float tb = acc / (1.f + expf(-acc));
    red[f] = tb * Wo2[f];
    __syncthreads();
    for (int s = 64; s > 0; s >>= 1) { if (f < s) red[f] += red[f+s]; __syncthreads(); }
    if (f == 0) d_h[i] = red[0];
}

__global__ void sum_kernel(float* __restrict__ out) {
    __shared__ double rd[256];
    int t = threadIdx.x;
    double a = 0.0;
    for (int i = t; i < NA; i += 256) a += (double)d_h[i];
    rd[t] = a; __syncthreads();
    for (int s = 128; s > 0; s >>= 1) { if (t < s) rd[t] += rd[t+s]; __syncthreads(); }
    if (t == 0) out[0] = (float)rd[0];
}

// ---------------- launch ------------------------------------------------------
extern "C" void kernel_launch(void* const* d_in, const int* in_sizes, int n_in,
                              void* d_out, int out_size) {
    const int*   Z    = (const int*)  d_in[0];
    const float* R    = (const float*)d_in[1];
    const float* emb  = (const float*)d_in[3];
    const float* Wq   = (const float*)d_in[4];
    const float* Wk   = (const float*)d_in[5];
    const float* Wv   = (const float*)d_in[6];
    const float* We_k = (const float*)d_in[7];
    const float* be_k = (const float*)d_in[8];
    const float* We_v = (const float*)d_in[9];
    const float* be_v = (const float*)d_in[10];
    const float* ln_g = (const float*)d_in[11];
    const float* ln_b = (const float*)d_in[12];
    const float* Wo1  = (const float*)d_in[13];
    const float* Wo2  = (const float*)d_in[14];
    float* out = (float*)d_out;

    static float* v0p = nullptr;
    static float* v1p = nullptr;
    static __half* e0p = nullptr;
    static __half* e1p = nullptr;
    static cudaStream_t s1 = nullptr;
    static cudaEvent_t evK = nullptr;
    static cudaEvent_t evE[NL];
    static cudaEvent_t evM[NL];
    if (!v0p) {
        cudaGetSymbolAddress((void**)&v0p, d_v0);
        cudaGetSymbolAddress((void**)&v1p, d_v1);
        cudaGetSymbolAddress((void**)&e0p, d_ekvh0);
        cudaGetSymbolAddress((void**)&e1p, d_ekvh1);
        cudaFuncSetAttribute(ekv_kernel, cudaFuncAttributeMaxDynamicSharedMemorySize, EKV_SMEM);
        cudaStreamCreateWithFlags(&s1, cudaStreamNonBlocking);
        cudaEventCreateWithFlags(&evK, cudaEventDisableTiming);
        for (int l = 0; l < NL; l++) {
            cudaEventCreateWithFlags(&evE[l], cudaEventDisableTiming);
            cudaEventCreateWithFlags(&evM[l], cudaEventDisableTiming);
        }
    }
    float*  vbufs[2] = { v0p, v1p };
    __half* ebufs[2] = { e0p, e1p };

    init_kernel<<<(NA*3*FDIM + 255)/256, 256>>>(Z, emb);
    knn_kernel<<<NA, 256>>>(R);
    cudaEventRecord(evK, 0);

    // pipeline: ekv chain on s1 (one layer ahead), qkv+message on stream 0
    cudaStreamWaitEvent(s1, evK, 0);
    ekv_kernel<<<dim3(NEDGE/EKV_EB, 2), 256, EKV_SMEM, s1>>>(We_k, be_k, We_v, be_v, 0, ebufs[0]);
    cudaEventRecord(evE[0], s1);

    for (int l = 0; l < NL; l++) {
        qkv_gemm<<<dim3(NA/128, 10), 256>>>(Wq, Wk, Wv, l);
        if (l + 1 < NL) {
            if (l >= 1) cudaStreamWaitEvent(s1, evM[l-1], 0);   // WAR: buffer (l+1)&1 was read by message(l-1)
            ekv_kernel<<<dim3(NEDGE/EKV_EB, 2), 256, EKV_SMEM, s1>>>(We_k, be_k, We_v, be_v, l + 1, ebufs[(l + 1) & 1]);
            cudaEventRecord(evE[l + 1], s1);
        }
        cudaStreamWaitEvent(0, evE[l], 0);
        message_kernel<<<NA, 128>>>(vbufs[l & 1], vbufs[(l + 1) & 1], ebufs[l & 1]);
        cudaEventRecord(evM[l], 0);
    }

    readout_kernel<<<NA, 128>>>(ln_g, ln_b, Wo1, Wo2);
    sum_kernel<<<1, 256>>>(out);
}

// round 6
// speedup vs baseline: 2.7976x; 1.6737x over previous
#include <cuda_runtime.h>
#include <cuda_fp16.h>
#include <math.h>

#define NA   4096
#define FDIM 128
#define NH   4
#define DH   32
#define KNN  15
#define NKR  50
#define NL   6
#define NEDGE (NA*KNN)
#define WT   16            // RBF window taps

// ekv kernel tiling: block = 128 edges x 256 cols (all live cols)
#define EKV_EB    128
#define EKV_EPASS 32       // edges per pass (8 groups of 4)
#define EKV_NPASS (EKV_EB/EKV_EPASS)
#define EKV_NGRP  8
#define RPAD      50
#define ECOL      256      // live output cols: [ek(128) | ev1(128)]

// ---------------- scratch (static device globals; no runtime alloc) --------
// NOTE: the reference's vector channel v (and m2/m3/vec_norm) never reaches
// the output (o only accumulates ds) — it is dead code and is not computed.
__device__ float  d_s[NA*FDIM];
__device__ float  d_o[NA*FDIM];
__device__ float  d_q[NA*FDIM];            // fp32 q (self-read only)
__device__ __half d_kvh[NA*256];           // fp16 [k(128) | val1(128)] (gathered)
__device__ __half d_ekvh0[NEDGE*ECOL];     // fp16 [ek(128)|ev1(128)] ping
__device__ __half d_ekvh1[NEDGE*ECOL];     // fp16 pong
__device__ float  d_cut[NEDGE];
__device__ float  d_dist[NEDGE];
__device__ int    d_idx[NEDGE];
__device__ float  d_h[NA];

// ---------------- init ------------------------------------------------------
__global__ void init_kernel(const int* __restrict__ Z, const float* __restrict__ emb) {
    int t = blockIdx.x * blockDim.x + threadIdx.x;
    if (t < NA*FDIM) {
        int i = t / FDIM, f = t % FDIM;
        d_s[t] = emb[Z[i]*FDIM + f];
        d_o[t] = 0.f;
    }
}

// ---------------- KNN + edge geometry ---------------------------------------
__global__ void knn_kernel(const float* __restrict__ R) {
    __shared__ float sd2[NA];
    __shared__ float rv[256];
    __shared__ int   rj[256];
    __shared__ int   sidx[KNN];

    int i = blockIdx.x, t = threadIdx.x;
    float rx = R[i*3], ry = R[i*3+1], rz = R[i*3+2];
    float sqi = rx*rx + ry*ry + rz*rz;

    for (int j = t; j < NA; j += 256) {
        float x = R[j*3], y = R[j*3+1], z = R[j*3+2];
        float sqj = x*x + y*y + z*z;
        float dot = rx*x + ry*y + rz*z;
        float d2  = fmaxf(sqi + sqj - 2.f*dot, 0.f);
        if (j == i) d2 = 1e9f;
        sd2[j] = d2;
    }
    __syncthreads();

    for (int k = 0; k < KNN; k++) {
        float bv = 1e30f; int bj = 0x7fffffff;
        for (int j = t; j < NA; j += 256) {
            float v = sd2[j];
            if (v < bv) { bv = v; bj = j; }
        }
        rv[t] = bv; rj[t] = bj;
        __syncthreads();
        for (int s = 128; s > 0; s >>= 1) {
            if (t < s) {
                float v2 = rv[t+s]; int j2 = rj[t+s];
                if (v2 < rv[t] || (v2 == rv[t] && j2 < rj[t])) { rv[t] = v2; rj[t] = j2; }
            }
            __syncthreads();
        }
        if (t == 0) { sidx[k] = rj[0]; sd2[rj[0]] = 1e9f; }
        __syncthreads();
    }

    if (t < KNN) {
        int j = sidx[t];
        float vx = R[j*3]   - rx;
        float vy = R[j*3+1] - ry;
        float vz = R[j*3+2] - rz;
        float dd = sqrtf(vx*vx + vy*vy + vz*vz + 1e-12f);
        int e = i*KNN + t;
        d_idx[e] = j;
        float c = (dd <= 5.f) ? 0.5f*(cosf(0.62831853071795864769f*dd) + 1.f) : 0.f;
        d_cut[e]  = c;
        d_dist[e] = dd;
    }
}

// ---------------- QKV GEMM: (4096x128)@(128x384) -> q fp32, k/val1 fp16 ------
__global__ __launch_bounds__(256) void qkv_gemm(const float* __restrict__ Wq,
                                                const float* __restrict__ Wk,
                                                const float* __restrict__ Wv, int l) {
    __shared__ float As[8*128];
    __shared__ float Bs[8*64];
    int bm = blockIdx.x, bn = blockIdx.y, t = threadIdx.x;
    int m0 = bm * 128;
    int cb = bn * 64;
    const float* B; int ldb, coff;
    if (cb < 128)       { B = Wq + l*FDIM*FDIM; ldb = FDIM; coff = cb; }
    else if (cb < 256)  { B = Wk + l*FDIM*FDIM; ldb = FDIM; coff = cb - 128; }
    else                { B = Wv + l*FDIM*384;  ldb = 384;  coff = cb - 256; }

    int tx = t & 15;
    int ty = t >> 4;
    float acc[8][4] = {};

    for (int k0 = 0; k0 < 128; k0 += 8) {
        {
            int k = t & 7, mb = t >> 3;
            #pragma unroll
            for (int p = 0; p < 4; p++) {
                int m = mb + p*32;
                As[k*128 + m] = d_s[(m0 + m)*FDIM + k0 + k];
            }
            if (t < 128) {
                int kk = t >> 4, n4 = t & 15;
                *(float4*)&Bs[kk*64 + n4*4] =
                    *(const float4*)&B[(k0 + kk)*ldb + coff + n4*4];
            }
        }
        __syncthreads();
        #pragma unroll
        for (int kk = 0; kk < 8; kk++) {
            float a[8], b[4];
            #pragma unroll
            for (int x = 0; x < 8; x++) a[x] = As[kk*128 + ty*8 + x];
            #pragma unroll
            for (int x = 0; x < 4; x++) b[x] = Bs[kk*64 + tx*4 + x];
            #pragma unroll
            for (int ix = 0; ix < 8; ix++)
                #pragma unroll
                for (int jx = 0; jx < 4; jx++)
                    acc[ix][jx] = fmaf(a[ix], b[jx], acc[ix][jx]);
        }
        __syncthreads();
    }
    if (cb < 128) {
        #pragma unroll
        for (int ix = 0; ix < 8; ix++) {
            float4 v = make_float4(acc[ix][0], acc[ix][1], acc[ix][2], acc[ix][3]);
            *(float4*)&d_q[(m0 + ty*8 + ix)*FDIM + cb + tx*4] = v;
        }
    } else {
        int kcol = cb - 128;     // 0..255 in kv layout
        #pragma unroll
        for (int ix = 0; ix < 8; ix++) {
            __half2 h0 = __floats2half2_rn(acc[ix][0], acc[ix][1]);
            __half2 h1 = __floats2half2_rn(acc[ix][2], acc[ix][3]);
            __half* out = d_kvh + (size_t)(m0 + ty*8 + ix)*256 + kcol + tx*4;
            *(__half2*)(out)     = h0;
            *(__half2*)(out + 2) = h1;
        }
    }
}

// ---------------- windowed edge filter + silu -> fp16 (256 live cols) --------
#define EKV_SM_WS    0
#define EKV_SM_EWS   (50*ECOL)
#define EKV_SM_BIAS  (EKV_SM_EWS + EKV_NGRP*RPAD*4)
#define EKV_SM_KBS   (EKV_SM_BIAS + ECOL)
#define EKV_SM_DDS   (EKV_SM_KBS + 32)
#define EKV_SM_CUTS  (EKV_SM_DDS + 32)
#define EKV_SM_RMIN  (EKV_SM_CUTS + 32)
#define EKV_SM_SPAN  (EKV_SM_RMIN + 8)
#define EKV_SMEM     ((EKV_SM_SPAN + 8) * 4)

__global__ __launch_bounds__(256, 3) void ekv_kernel(const float* __restrict__ Wek,
                                                     const float* __restrict__ bek,
                                                     const float* __restrict__ Wev,
                                                     const float* __restrict__ bev,
                                                     int l, __half* __restrict__ ekv_out) {
    extern __shared__ float sm[];
    float* Ws    = sm + EKV_SM_WS;
    float* ews   = sm + EKV_SM_EWS;
    float* biasS = sm + EKV_SM_BIAS;
    int*   kbs   = (int*)(sm + EKV_SM_KBS);
    float* dds   = sm + EKV_SM_DDS;
    float* cuts  = sm + EKV_SM_CUTS;
    int*   rminS = (int*)(sm + EKV_SM_RMIN);
    int*   spanS = (int*)(sm + EKV_SM_SPAN);

    int tid  = threadIdx.x;
    int lane = tid & 31;
    int g    = tid >> 5;
    int eblk = blockIdx.x * EKV_EB;

    // weights: [We_k(128) | We_v first 128 cols], per-row float4 count = 64
    {
        float4* Ws4 = (float4*)Ws;
        const float4* Wek4 = (const float4*)(Wek + l*50*FDIM);
        const float4* Wev4 = (const float4*)(Wev + l*50*384);
        for (int q = tid; q < 50*64; q += 256) {
            int row = q >> 6;
            int c4  = q & 63;
            Ws4[q] = (c4 < 32) ? Wek4[row*32 + c4] : Wev4[row*96 + (c4 - 32)];
        }
        if (tid < 64) {
            float4 b = (tid < 32) ? ((const float4*)(bek + l*FDIM))[tid]
                                  : ((const float4*)(bev + l*384))[tid - 32];
            ((float4*)biasS)[tid] = b;
        }
    }

    int c0 = lane * 4;

    for (int pass = 0; pass < EKV_NPASS; pass++) {
        int e0 = eblk + pass * EKV_EPASS;
        __syncthreads();

        {
            float4 z = make_float4(0.f, 0.f, 0.f, 0.f);
            for (int u = tid; u < EKV_NGRP*RPAD; u += 256)
                ((float4*)ews)[u] = z;
        }
        if (tid < EKV_EPASS) {
            int ge = e0 + tid;
            float dd = d_dist[ge];
            float fi = dd * (49.0f/5.0f);
            int k0 = (int)floorf(fi + 0.5f) - 7;
            k0 = max(0, min(50 - WT, k0));
            kbs[tid]  = k0;
            dds[tid]  = dd;
            cuts[tid] = d_cut[ge];
        }
        __syncthreads();
        if (tid < EKV_NGRP) {
            int a0 = kbs[tid*4], a1 = kbs[tid*4+1], a2 = kbs[tid*4+2], a3 = kbs[tid*4+3];
            int rmin = min(min(a0,a1), min(a2,a3));
            int rmax = max(max(a0,a1), max(a2,a3)) + WT;
            rminS[tid] = rmin;
            spanS[tid] = rmax - rmin;
        }
        __syncthreads();
        for (int u = tid; u < EKV_EPASS*WT; u += 256) {
            int e = u >> 4, tt = u & 15;
            int gg = e >> 2;
            int kk = kbs[e];
            int row = kk + tt - rminS[gg];
            float mu = (float)(kk + tt) * (5.0f/49.0f);
            float df = dds[e] - mu;
            ews[(gg*RPAD + row)*4 + (e & 3)] = __expf(-df*df*50.0f) * cuts[e];
        }
        __syncthreads();

        int rmin = rminS[g];
        int span = spanS[g];
        const float* wp = Ws + rmin*ECOL + c0;
        const float4* ep = (const float4*)(ews + g*RPAD*4);

        float4 a00 = make_float4(0,0,0,0), a01 = a00;
        float4 a10 = a00, a11 = a00;
        float4 a20 = a00, a21 = a00;
        float4 a30 = a00, a31 = a00;

        for (int r = 0; r < span; r++) {
            float4 ew = ep[r];
            float4 w0 = *(const float4*)(wp);
            float4 w1 = *(const float4*)(wp + 128);
            wp += ECOL;
            a00.x = fmaf(ew.x, w0.x, a00.x); a00.y = fmaf(ew.x, w0.y, a00.y);
            a00.z = fmaf(ew.x, w0.z, a00.z); a00.w = fmaf(ew.x, w0.w, a00.w);
            a01.x = fmaf(ew.x, w1.x, a01.x); a01.y = fmaf(ew.x, w1.y, a01.y);
            a01.z = fmaf(ew.x, w1.z, a01.z); a01.w = fmaf(ew.x, w1.w, a01.w);

            a10.x = fmaf(ew.y, w0.x, a10.x); a10.y = fmaf(ew.y, w0.y, a10.y);
            a10.z = fmaf(ew.y, w0.z, a10.z); a10.w = fmaf(ew.y, w0.w, a10.w);
            a11.x = fmaf(ew.y, w1.x, a11.x); a11.y = fmaf(ew.y, w1.y, a11.y);
            a11.z = fmaf(ew.y, w1.z, a11.z); a11.w = fmaf(ew.y, w1.w, a11.w);

            a20.x = fmaf(ew.z, w0.x, a20.x); a20.y = fmaf(ew.z, w0.y, a20.y);
            a20.z = fmaf(ew.z, w0.z, a20.z); a20.w = fmaf(ew.z, w0.w, a20.w);
            a21.x = fmaf(ew.z, w1.x, a21.x); a21.y = fmaf(ew.z, w1.y, a21.y);
            a21.z = fmaf(ew.z, w1.z, a21.z); a21.w = fmaf(ew.z, w1.w, a21.w);

            a30.x = fmaf(ew.w, w0.x, a30.x); a30.y = fmaf(ew.w, w0.y, a30.y);
            a30.z = fmaf(ew.w, w0.z, a30.z); a30.w = fmaf(ew.w, w0.w, a30.w);
            a31.x = fmaf(ew.w, w1.x, a31.x); a31.y = fmaf(ew.w, w1.y, a31.y);
            a31.z = fmaf(ew.w, w1.z, a31.z); a31.w = fmaf(ew.w, w1.w, a31.w);
        }

        float4 b0 = *(const float4*)(biasS + c0);
        float4 b1 = *(const float4*)(biasS + c0 + 128);
        float4 accs[4][2] = {{a00,a01},{a10,a11},{a20,a21},{a30,a31}};
        float4 bs[2] = {b0,b1};
        #pragma unroll
        for (int e = 0; e < 4; e++) {
            __half* out = ekv_out + (size_t)(e0 + g*4 + e)*ECOL + c0;
            #pragma unroll
            for (int p = 0; p < 2; p++) {
                float4 x = accs[e][p];
                x.x += bs[p].x; x.y += bs[p].y; x.z += bs[p].z; x.w += bs[p].w;
                float s0 = x.x / (1.f + __expf(-x.x));
                float s1 = x.y / (1.f + __expf(-x.y));
                float s2 = x.z / (1.f + __expf(-x.z));
                float s3 = x.w / (1.f + __expf(-x.w));
                *(__half2*)(out + p*128)     = __floats2half2_rn(s0, s1);
                *(__half2*)(out + p*128 + 2) = __floats2half2_rn(s2, s3);
            }
        }
    }
}

// ---------------- fused attention message kernel (scalar channel only) ------
__global__ void message_kernel(const __half* __restrict__ ekv) {
    __shared__ float scut[KNN];
    __shared__ float slog[KNN*NH];
    __shared__ float sattn[KNN*NH];
    __shared__ int   sj[KNN];

    int i = blockIdx.x, f = threadIdx.x;
    int w = f >> 5, lane = f & 31;

    if (f < KNN) { int e = i*KNN + f; sj[f] = d_idx[e]; scut[f] = d_cut[e]; }
    __syncthreads();

    float q = d_q[i*FDIM + f];

    // logits
    #pragma unroll 3
    for (int k = 0; k < KNN; k++) {
        int j = sj[k];
        float kf  = __half2float(d_kvh[(size_t)j*256 + f]);
        float ekf = __half2float(ekv[(size_t)(i*KNN + k)*ECOL + f]);
        float p = q * kf * ekf;
        #pragma unroll
        for (int off = 16; off; off >>= 1) p += __shfl_down_sync(0xffffffffu, p, off);
        if (lane == 0) slog[k*NH + w] = p * 0.125f;
    }
    __syncthreads();

    // softmax over k per head, times cutoff
    {
        float lv = (lane < KNN) ? slog[lane*NH + w] : -1e30f;
        float mx = lv;
        #pragma unroll
        for (int off = 16; off; off >>= 1) mx = fmaxf(mx, __shfl_xor_sync(0xffffffffu, mx, off));
        float ex = (lane < KNN) ? expf(lv - mx) : 0.f;
        float sm = ex;
        #pragma unroll
        for (int off = 16; off; off >>= 1) sm += __shfl_xor_sync(0xffffffffu, sm, off);
        if (lane < KNN) sattn[lane*NH + w] = ex / sm * scut[lane];
    }
    __syncthreads();

    // scalar message
    float ds = 0.f;
    #pragma unroll 5
    for (int k = 0; k < KNN; k++) {
        int j  = sj[k];
        float wf = sattn[k*NH + w];
        float va = __half2float(d_kvh[(size_t)j*256 + 128 + f]);
        float ev = __half2float(ekv[(size_t)(i*KNN + k)*ECOL + 128 + f]);
        ds = fmaf(wf, va * ev, ds);
    }
    d_s[i*FDIM + f] += ds;
    d_o[i*FDIM + f] += ds;
}

// ---------------- layernorm + readout ---------------------------------------
__global__ void readout_kernel(const float* __restrict__ ln_g, const float* __restrict__ ln_b,
                               const float* __restrict__ Wo1,  const float* __restrict__ Wo2) {
    __shared__ float red[128];
    __shared__ float son[128];
    int i = blockIdx.x, f = threadIdx.x;
    float x = d_o[i*FDIM + f];

    red[f] = x; __syncthreads();
    for (int s = 64; s > 0; s >>= 1) { if (f < s) red[f] += red[f+s]; __syncthreads(); }
    float mean = red[0] * (1.f/128.f);
    __syncthreads();

    float dx = x - mean;
    red[f] = dx*dx; __syncthreads();
    for (int s = 64; s > 0; s >>= 1) { if (f < s) red[f] += red[f+s]; __syncthreads(); }
    float var = red[0] * (1.f/128.f);
    __syncthreads();

    float on = dx * (1.f / sqrtf(var + 1e-5f)) * ln_g[f] + ln_b[f];
    son[f] = on; __syncthreads();

    float acc = 0.f;
    #pragma unroll 8
    for (int g = 0; g < 128; g++) acc = fmaf(son[g], Wo1[g*FDIM + f], acc);
    float tb = acc / (1.f + expf(-acc));
    red[f] = tb * Wo2[f];
    __syncthreads();
    for (int s = 64; s > 0; s >>= 1) { if (f < s) red[f] += red[f+s]; __syncthreads(); }
    if (f == 0) d_h[i] = red[0];
}

__global__ void sum_kernel(float* __restrict__ out) {
    __shared__ double rd[256];
    int t = threadIdx.x;
    double a = 0.0;
    for (int i = t; i < NA; i += 256) a += (double)d_h[i];
    rd[t] = a; __syncthreads();
    for (int s = 128; s > 0; s >>= 1) { if (t < s) rd[t] += rd[t+s]; __syncthreads(); }
    if (t == 0) out[0] = (float)rd[0];
}

// ---------------- launch ------------------------------------------------------
extern "C" void kernel_launch(void* const* d_in, const int* in_sizes, int n_in,
                              void* d_out, int out_size) {
    const int*   Z    = (const int*)  d_in[0];
    const float* R    = (const float*)d_in[1];
    const float* emb  = (const float*)d_in[3];
    const float* Wq   = (const float*)d_in[4];
    const float* Wk   = (const float*)d_in[5];
    const float* Wv   = (const float*)d_in[6];
    const float* We_k = (const float*)d_in[7];
    const float* be_k = (const float*)d_in[8];
    const float* We_v = (const float*)d_in[9];
    const float* be_v = (const float*)d_in[10];
    const float* ln_g = (const float*)d_in[11];
    const float* ln_b = (const float*)d_in[12];
    const float* Wo1  = (const float*)d_in[13];
    const float* Wo2  = (const float*)d_in[14];
    float* out = (float*)d_out;

    static __half* e0p = nullptr;
    static __half* e1p = nullptr;
    static cudaStream_t s1 = nullptr;
    static cudaEvent_t evK = nullptr;
    static cudaEvent_t evE[NL];
    static cudaEvent_t evM[NL];
    if (!e0p) {
        cudaGetSymbolAddress((void**)&e0p, d_ekvh0);
        cudaGetSymbolAddress((void**)&e1p, d_ekvh1);
        cudaFuncSetAttribute(ekv_kernel, cudaFuncAttributeMaxDynamicSharedMemorySize, EKV_SMEM);
        cudaStreamCreateWithFlags(&s1, cudaStreamNonBlocking);
        cudaEventCreateWithFlags(&evK, cudaEventDisableTiming);
        for (int l = 0; l < NL; l++) {
            cudaEventCreateWithFlags(&evE[l], cudaEventDisableTiming);
            cudaEventCreateWithFlags(&evM[l], cudaEventDisableTiming);
        }
    }
    __half* ebufs[2] = { e0p, e1p };

    init_kernel<<<(NA*FDIM + 255)/256, 256>>>(Z, emb);
    knn_kernel<<<NA, 256>>>(R);
    cudaEventRecord(evK, 0);

    // pipeline: ekv chain on s1 (one layer ahead), qkv+message on stream 0
    cudaStreamWaitEvent(s1, evK, 0);
    ekv_kernel<<<NEDGE/EKV_EB, 256, EKV_SMEM, s1>>>(We_k, be_k, We_v, be_v, 0, ebufs[0]);
    cudaEventRecord(evE[0], s1);

    for (int l = 0; l < NL; l++) {
        qkv_gemm<<<dim3(NA/128, 6), 256>>>(Wq, Wk, Wv, l);
        if (l + 1 < NL) {
            if (l >= 1) cudaStreamWaitEvent(s1, evM[l-1], 0);   // WAR on ping-pong buffer
            ekv_kernel<<<NEDGE/EKV_EB, 256, EKV_SMEM, s1>>>(We_k, be_k, We_v, be_v, l + 1, ebufs[(l + 1) & 1]);
            cudaEventRecord(evE[l + 1], s1);
        }
        cudaStreamWaitEvent(0, evE[l], 0);
        message_kernel<<<NA, 128>>>(ebufs[l & 1]);
        cudaEventRecord(evM[l], 0);
    }

    readout_kernel<<<NA, 128>>>(ln_g, ln_b, Wo1, Wo2);
    sum_kernel<<<1, 256>>>(out);
}

// round 7
// speedup vs baseline: 2.8190x; 1.0076x over previous
#include <cuda_runtime.h>
#include <cuda_fp16.h>
#include <math.h>

#define NA   4096
#define FDIM 128
#define NH   4
#define DH   32
#define KNN  15
#define NKR  50
#define NL   6
#define NEDGE (NA*KNN)
#define WT   16            // RBF window taps

// ekv kernel tiling: block = 128 edges x 256 cols, warp = 4-edge group
#define EKV_EB    128
#define EKV_NPASS 4
#define RPAD      50
#define ECOL      256      // live output cols: [ek(128) | ev1(128)]

// ---------------- scratch (static device globals; no runtime alloc) --------
// The reference's vector channel v (m2/m3/vec_norm) never reaches the output
// (o only accumulates ds) — dead code, not computed.
__device__ float  d_s[NA*FDIM];
__device__ float  d_o[NA*FDIM];
__device__ float  d_q[NA*FDIM];            // fp32 q (self-read only)
__device__ __half d_kvh[NA*256];           // fp16 [k(128) | val1(128)] (gathered)
__device__ __half d_ekvh0[NEDGE*ECOL];     // fp16 [ek(128)|ev1(128)] ping
__device__ __half d_ekvh1[NEDGE*ECOL];     // fp16 pong
__device__ float  d_cut[NEDGE];
__device__ float  d_dist[NEDGE];
__device__ int    d_idx[NEDGE];
__device__ float  d_h[NA];

// ---------------- init ------------------------------------------------------
__global__ void init_kernel(const int* __restrict__ Z, const float* __restrict__ emb) {
    int t = blockIdx.x * blockDim.x + threadIdx.x;
    if (t < NA*FDIM) {
        int i = t / FDIM, f = t % FDIM;
        d_s[t] = emb[Z[i]*FDIM + f];
        d_o[t] = 0.f;
    }
}

// ---------------- KNN + edge geometry ---------------------------------------
__global__ void knn_kernel(const float* __restrict__ R) {
    __shared__ float sd2[NA];
    __shared__ float rv[256];
    __shared__ int   rj[256];
    __shared__ int   sidx[KNN];

    int i = blockIdx.x, t = threadIdx.x;
    float rx = R[i*3], ry = R[i*3+1], rz = R[i*3+2];
    float sqi = rx*rx + ry*ry + rz*rz;

    for (int j = t; j < NA; j += 256) {
        float x = R[j*3], y = R[j*3+1], z = R[j*3+2];
        float sqj = x*x + y*y + z*z;
        float dot = rx*x + ry*y + rz*z;
        float d2  = fmaxf(sqi + sqj - 2.f*dot, 0.f);
        if (j == i) d2 = 1e9f;
        sd2[j] = d2;
    }
    __syncthreads();

    for (int k = 0; k < KNN; k++) {
        float bv = 1e30f; int bj = 0x7fffffff;
        for (int j = t; j < NA; j += 256) {
            float v = sd2[j];
            if (v < bv) { bv = v; bj = j; }
        }
        rv[t] = bv; rj[t] = bj;
        __syncthreads();
        for (int s = 128; s > 0; s >>= 1) {
            if (t < s) {
                float v2 = rv[t+s]; int j2 = rj[t+s];
                if (v2 < rv[t] || (v2 == rv[t] && j2 < rj[t])) { rv[t] = v2; rj[t] = j2; }
            }
            __syncthreads();
        }
        if (t == 0) { sidx[k] = rj[0]; sd2[rj[0]] = 1e9f; }
        __syncthreads();
    }

    if (t < KNN) {
        int j = sidx[t];
        float vx = R[j*3]   - rx;
        float vy = R[j*3+1] - ry;
        float vz = R[j*3+2] - rz;
        float dd = sqrtf(vx*vx + vy*vy + vz*vz + 1e-12f);
        int e = i*KNN + t;
        d_idx[e] = j;
        float c = (dd <= 5.f) ? 0.5f*(cosf(0.62831853071795864769f*dd) + 1.f) : 0.f;
        d_cut[e]  = c;
        d_dist[e] = dd;
    }
}

// ---------------- QKV GEMM: (4096x128)@(128x384), 64x64 tiles, 128 thr ------
__global__ __launch_bounds__(128) void qkv_gemm(const float* __restrict__ Wq,
                                                const float* __restrict__ Wk,
                                                const float* __restrict__ Wv, int l) {
    __shared__ float As[8*64];    // [k][m]
    __shared__ float Bs[8*64];    // [k][n]
    int bm = blockIdx.x, bn = blockIdx.y, t = threadIdx.x;
    int m0 = bm * 64;
    int cb = bn * 64;
    const float* B; int ldb, coff;
    if (cb < 128)       { B = Wq + l*FDIM*FDIM; ldb = FDIM; coff = cb; }
    else if (cb < 256)  { B = Wk + l*FDIM*FDIM; ldb = FDIM; coff = cb - 128; }
    else                { B = Wv + l*FDIM*384;  ldb = 384;  coff = cb - 256; }

    int tx = t & 15;      // n group: 4 cols
    int ty = t >> 4;      // m group: 8 rows (0..7)
    float acc[8][4] = {};

    for (int k0 = 0; k0 < 128; k0 += 8) {
        {
            int k = t & 7, mb = t >> 3;     // mb 0..15
            #pragma unroll
            for (int p = 0; p < 4; p++) {
                int m = mb + p*16;
                As[k*64 + m] = d_s[(m0 + m)*FDIM + k0 + k];
            }
            int kk = t >> 4, n4 = t & 15;
            *(float4*)&Bs[kk*64 + n4*4] =
                *(const float4*)&B[(k0 + kk)*ldb + coff + n4*4];
        }
        __syncthreads();
        #pragma unroll
        for (int kk = 0; kk < 8; kk++) {
            float a[8], b[4];
            #pragma unroll
            for (int x = 0; x < 8; x++) a[x] = As[kk*64 + ty*8 + x];
            #pragma unroll
            for (int x = 0; x < 4; x++) b[x] = Bs[kk*64 + tx*4 + x];
            #pragma unroll
            for (int ix = 0; ix < 8; ix++)
                #pragma unroll
                for (int jx = 0; jx < 4; jx++)
                    acc[ix][jx] = fmaf(a[ix], b[jx], acc[ix][jx]);
        }
        __syncthreads();
    }
    if (cb < 128) {
        #pragma unroll
        for (int ix = 0; ix < 8; ix++) {
            float4 v = make_float4(acc[ix][0], acc[ix][1], acc[ix][2], acc[ix][3]);
            *(float4*)&d_q[(m0 + ty*8 + ix)*FDIM + cb + tx*4] = v;
        }
    } else {
        int kcol = cb - 128;
        #pragma unroll
        for (int ix = 0; ix < 8; ix++) {
            __half2 h0 = __floats2half2_rn(acc[ix][0], acc[ix][1]);
            __half2 h1 = __floats2half2_rn(acc[ix][2], acc[ix][3]);
            __half* out = d_kvh + (size_t)(m0 + ty*8 + ix)*256 + kcol + tx*4;
            *(__half2*)(out)     = h0;
            *(__half2*)(out + 2) = h1;
        }
    }
}

// ---------------- windowed edge filter + silu -> fp16, warp-autonomous ------
// smem: Ws[50*256] fp32 | biasS[256] | ews[8 warps][RPAD*4]
#define EKV_SM_BIAS  (50*ECOL)
#define EKV_SM_EWS   (EKV_SM_BIAS + ECOL)
#define EKV_SMEM     ((EKV_SM_EWS + 8*RPAD*4) * 4)

__global__ __launch_bounds__(256, 3) void ekv_kernel(const float* __restrict__ Wek,
                                                     const float* __restrict__ bek,
                                                     const float* __restrict__ Wev,
                                                     const float* __restrict__ bev,
                                                     int l, __half* __restrict__ ekv_out) {
    extern __shared__ float sm[];
    float* Ws    = sm;
    float* biasS = sm + EKV_SM_BIAS;
    float* ews   = sm + EKV_SM_EWS;

    int tid  = threadIdx.x;
    int lane = tid & 31;
    int g    = tid >> 5;
    int eblk = blockIdx.x * EKV_EB;

    // cooperative load: weights [We_k(128) | We_v first 128 cols] + bias
    {
        float4* Ws4 = (float4*)Ws;
        const float4* Wek4 = (const float4*)(Wek + l*50*FDIM);
        const float4* Wev4 = (const float4*)(Wev + l*50*384);
        for (int q = tid; q < 50*64; q += 256) {
            int row = q >> 6;
            int c4  = q & 63;
            Ws4[q] = (c4 < 32) ? Wek4[row*32 + c4] : Wev4[row*96 + (c4 - 32)];
        }
        if (tid < 64) {
            float4 b = (tid < 32) ? ((const float4*)(bek + l*FDIM))[tid]
                                  : ((const float4*)(bev + l*384))[tid - 32];
            ((float4*)biasS)[tid] = b;
        }
    }
    __syncthreads();    // the only block-wide sync

    int c0 = lane * 4;
    float* myews = ews + g * (RPAD*4);

    float4 b0 = *(const float4*)(biasS + c0);
    float4 b1 = *(const float4*)(biasS + c0 + 128);

    #pragma unroll
    for (int pass = 0; pass < EKV_NPASS; pass++) {
        int e0 = eblk + pass*32 + g*4;

        // lane e<4 loads edge e; broadcast via shfl
        float dd_l = 0.f, cut_l = 0.f; int k0_l = 0;
        if (lane < 4) {
            dd_l  = d_dist[e0 + lane];
            cut_l = d_cut[e0 + lane];
            float fi = dd_l * (49.0f/5.0f);
            int kk = (int)floorf(fi + 0.5f) - 7;
            k0_l = max(0, min(50 - WT, kk));
        }
        int   k0v[4]; float ddv[4], cutv[4];
        #pragma unroll
        for (int e = 0; e < 4; e++) {
            k0v[e]  = __shfl_sync(0xffffffffu, k0_l, e);
            ddv[e]  = __shfl_sync(0xffffffffu, dd_l, e);
            cutv[e] = __shfl_sync(0xffffffffu, cut_l, e);
        }
        int rmin = min(min(k0v[0], k0v[1]), min(k0v[2], k0v[3]));
        int span = max(max(k0v[0], k0v[1]), max(k0v[2], k0v[3])) + WT - rmin;

        __syncwarp();   // prior pass's FMA reads of myews complete
        // zero pad (50 float4 rows per warp)
        {
            float4 z = make_float4(0.f, 0.f, 0.f, 0.f);
            for (int r = lane; r < RPAD; r += 32)
                ((float4*)myews)[r] = z;
        }
        __syncwarp();
        // scatter 64 taps (2 per lane)
        #pragma unroll
        for (int u = lane; u < 64; u += 32) {
            int e = u >> 4, tt = u & 15;
            int row = k0v[e] + tt - rmin;
            float mu = (float)(k0v[e] + tt) * (5.0f/49.0f);
            float df = ddv[e] - mu;
            myews[row*4 + e] = __expf(-df*df*50.0f) * cutv[e];
        }
        __syncwarp();

        const float* wp = Ws + rmin*ECOL + c0;
        const float4* ep = (const float4*)myews;

        float4 a00 = make_float4(0,0,0,0), a01 = a00;
        float4 a10 = a00, a11 = a00;
        float4 a20 = a00, a21 = a00;
        float4 a30 = a00, a31 = a00;

        for (int r = 0; r < span; r++) {
            float4 ew = ep[r];
            float4 w0 = *(const float4*)(wp);
            float4 w1 = *(const float4*)(wp + 128);
            wp += ECOL;
            a00.x = fmaf(ew.x, w0.x, a00.x); a00.y = fmaf(ew.x, w0.y, a00.y);
            a00.z = fmaf(ew.x, w0.z, a00.z); a00.w = fmaf(ew.x, w0.w, a00.w);
            a01.x = fmaf(ew.x, w1.x, a01.x); a01.y = fmaf(ew.x, w1.y, a01.y);
            a01.z = fmaf(ew.x, w1.z, a01.z); a01.w = fmaf(ew.x, w1.w, a01.w);

            a10.x = fmaf(ew.y, w0.x, a10.x); a10.y = fmaf(ew.y, w0.y, a10.y);
            a10.z = fmaf(ew.y, w0.z, a10.z); a10.w = fmaf(ew.y, w0.w, a10.w);
            a11.x = fmaf(ew.y, w1.x, a11.x); a11.y = fmaf(ew.y, w1.y, a11.y);
            a11.z = fmaf(ew.y, w1.z, a11.z); a11.w = fmaf(ew.y, w1.w, a11.w);

            a20.x = fmaf(ew.z, w0.x, a20.x); a20.y = fmaf(ew.z, w0.y, a20.y);
            a20.z = fmaf(ew.z, w0.z, a20.z); a20.w = fmaf(ew.z, w0.w, a20.w);
            a21.x = fmaf(ew.z, w1.x, a21.x); a21.y = fmaf(ew.z, w1.y, a21.y);
            a21.z = fmaf(ew.z, w1.z, a21.z); a21.w = fmaf(ew.z, w1.w, a21.w);

            a30.x = fmaf(ew.w, w0.x, a30.x); a30.y = fmaf(ew.w, w0.y, a30.y);
            a30.z = fmaf(ew.w, w0.z, a30.z); a30.w = fmaf(ew.w, w0.w, a30.w);
            a31.x = fmaf(ew.w, w1.x, a31.x); a31.y = fmaf(ew.w, w1.y, a31.y);
            a31.z = fmaf(ew.w, w1.z, a31.z); a31.w = fmaf(ew.w, w1.w, a31.w);
        }

        float4 accs[4][2] = {{a00,a01},{a10,a11},{a20,a21},{a30,a31}};
        float4 bs[2] = {b0,b1};
        #pragma unroll
        for (int e = 0; e < 4; e++) {
            __half* out = ekv_out + (size_t)(e0 + e)*ECOL + c0;
            #pragma unroll
            for (int p = 0; p < 2; p++) {
                float4 x = accs[e][p];
                x.x += bs[p].x; x.y += bs[p].y; x.z += bs[p].z; x.w += bs[p].w;
                float s0 = x.x / (1.f + __expf(-x.x));
                float s1 = x.y / (1.f + __expf(-x.y));
                float s2 = x.z / (1.f + __expf(-x.z));
                float s3 = x.w / (1.f + __expf(-x.w));
                *(__half2*)(out + p*128)     = __floats2half2_rn(s0, s1);
                *(__half2*)(out + p*128 + 2) = __floats2half2_rn(s2, s3);
            }
        }
    }
}

// ---------------- fused attention message kernel (single gather pass) -------
__global__ void message_kernel(const __half* __restrict__ ekv) {
    __shared__ float scut[KNN];
    __shared__ float slog[KNN*NH];
    __shared__ float sattn[KNN*NH];
    __shared__ int   sj[KNN];

    int i = blockIdx.x, f = threadIdx.x;
    int w = f >> 5, lane = f & 31;

    if (f < KNN) { int e = i*KNN + f; sj[f] = d_idx[e]; scut[f] = d_cut[e]; }
    __syncthreads();

    float q = d_q[i*FDIM + f];
    float prod[KNN];

    // single gather pass: logits + cache va*ev
    #pragma unroll
    for (int k = 0; k < KNN; k++) {
        int j = sj[k];
        const __half* kvp = d_kvh + (size_t)j*256 + f;
        const __half* evp = ekv + (size_t)(i*KNN + k)*ECOL + f;
        float kf  = __half2float(kvp[0]);
        float va  = __half2float(kvp[128]);
        float ekf = __half2float(evp[0]);
        float ev  = __half2float(evp[128]);
        prod[k] = va * ev;
        float p = q * kf * ekf;
        #pragma unroll
        for (int off = 16; off; off >>= 1) p += __shfl_down_sync(0xffffffffu, p, off);
        if (lane == 0) slog[k*NH + w] = p * 0.125f;
    }
    __syncthreads();

    // softmax over k per head, times cutoff
    {
        float lv = (lane < KNN) ? slog[lane*NH + w] : -1e30f;
        float mx = lv;
        #pragma unroll
        for (int off = 16; off; off >>= 1) mx = fmaxf(mx, __shfl_xor_sync(0xffffffffu, mx, off));
        float ex = (lane < KNN) ? expf(lv - mx) : 0.f;
        float sm = ex;
        #pragma unroll
        for (int off = 16; off; off >>= 1) sm += __shfl_xor_sync(0xffffffffu, sm, off);
        if (lane < KNN) sattn[lane*NH + w] = ex / sm * scut[lane];
    }
    __syncthreads();

    float ds = 0.f;
    #pragma unroll
    for (int k = 0; k < KNN; k++)
        ds = fmaf(sattn[k*NH + w], prod[k], ds);
    d_s[i*FDIM + f] += ds;
    d_o[i*FDIM + f] += ds;
}

// ---------------- layernorm + readout ---------------------------------------
__global__ void readout_kernel(const float* __restrict__ ln_g, const float* __restrict__ ln_b,
                               const float* __restrict__ Wo1,  const float* __restrict__ Wo2) {
    __shared__ float red[128];
    __shared__ float son[128];
    int i = blockIdx.x, f = threadIdx.x;
    float x = d_o[i*FDIM + f];

    red[f] = x; __syncthreads();
    for (int s = 64; s > 0; s >>= 1) { if (f < s) red[f] += red[f+s]; __syncthreads(); }
    float mean = red[0] * (1.f/128.f);
    __syncthreads();

    float dx = x - mean;
    red[f] = dx*dx; __syncthreads();
    for (int s = 64; s > 0; s >>= 1) { if (f < s) red[f] += red[f+s]; __syncthreads(); }
    float var = red[0] * (1.f/128.f);
    __syncthreads();

    float on = dx * (1.f / sqrtf(var + 1e-5f)) * ln_g[f] + ln_b[f];
    son[f] = on; __syncthreads();

    float acc = 0.f;
    #pragma unroll 8
    for (int g = 0; g < 128; g++) acc = fmaf(son[g], Wo1[g*FDIM + f], acc);
    float tb = acc / (1.f + expf(-acc));
    red[f] = tb * Wo2[f];
    __syncthreads();
    for (int s = 64; s > 0; s >>= 1) { if (f < s) red[f] += red[f+s]; __syncthreads(); }
    if (f == 0) d_h[i] = red[0];
}

__global__ void sum_kernel(float* __restrict__ out) {
    __shared__ double rd[256];
    int t = threadIdx.x;
    double a = 0.0;
    for (int i = t; i < NA; i += 256) a += (double)d_h[i];
    rd[t] = a; __syncthreads();
    for (int s = 128; s > 0; s >>= 1) { if (t < s) rd[t] += rd[t+s]; __syncthreads(); }
    if (t == 0) out[0] = (float)rd[0];
}

// ---------------- launch ------------------------------------------------------
extern "C" void kernel_launch(void* const* d_in, const int* in_sizes, int n_in,
                              void* d_out, int out_size) {
    const int*   Z    = (const int*)  d_in[0];
    const float* R    = (const float*)d_in[1];
    const float* emb  = (const float*)d_in[3];
    const float* Wq   = (const float*)d_in[4];
    const float* Wk   = (const float*)d_in[5];
    const float* Wv   = (const float*)d_in[6];
    const float* We_k = (const float*)d_in[7];
    const float* be_k = (const float*)d_in[8];
    const float* We_v = (const float*)d_in[9];
    const float* be_v = (const float*)d_in[10];
    const float* ln_g = (const float*)d_in[11];
    const float* ln_b = (const float*)d_in[12];
    const float* Wo1  = (const float*)d_in[13];
    const float* Wo2  = (const float*)d_in[14];
    float* out = (float*)d_out;

    static __half* e0p = nullptr;
    static __half* e1p = nullptr;
    static cudaStream_t s1 = nullptr;
    static cudaEvent_t evK = nullptr;
    static cudaEvent_t evE[NL];
    static cudaEvent_t evM[NL];
    if (!e0p) {
        cudaGetSymbolAddress((void**)&e0p, d_ekvh0);
        cudaGetSymbolAddress((void**)&e1p, d_ekvh1);
        cudaFuncSetAttribute(ekv_kernel, cudaFuncAttributeMaxDynamicSharedMemorySize, EKV_SMEM);
        cudaStreamCreateWithFlags(&s1, cudaStreamNonBlocking);
        cudaEventCreateWithFlags(&evK, cudaEventDisableTiming);
        for (int l = 0; l < NL; l++) {
            cudaEventCreateWithFlags(&evE[l], cudaEventDisableTiming);
            cudaEventCreateWithFlags(&evM[l], cudaEventDisableTiming);
        }
    }
    __half* ebufs[2] = { e0p, e1p };

    init_kernel<<<(NA*FDIM + 255)/256, 256>>>(Z, emb);
    knn_kernel<<<NA, 256>>>(R);
    cudaEventRecord(evK, 0);

    // pipeline: ekv chain on s1 (one layer ahead), qkv+message on stream 0
    cudaStreamWaitEvent(s1, evK, 0);
    ekv_kernel<<<NEDGE/EKV_EB, 256, EKV_SMEM, s1>>>(We_k, be_k, We_v, be_v, 0, ebufs[0]);
    cudaEventRecord(evE[0], s1);

    for (int l = 0; l < NL; l++) {
        qkv_gemm<<<dim3(NA/64, 6), 128>>>(Wq, Wk, Wv, l);
        if (l + 1 < NL) {
            if (l >= 1) cudaStreamWaitEvent(s1, evM[l-1], 0);   // WAR on ping-pong buffer
            ekv_kernel<<<NEDGE/EKV_EB, 256, EKV_SMEM, s1>>>(We_k, be_k, We_v, be_v, l + 1, ebufs[(l + 1) & 1]);
            cudaEventRecord(evE[l + 1], s1);
        }
        cudaStreamWaitEvent(0, evE[l], 0);
        message_kernel<<<NA, 128>>>(ebufs[l & 1]);
        cudaEventRecord(evM[l], 0);
    }

    readout_kernel<<<NA, 128>>>(ln_g, ln_b, Wo1, Wo2);
    sum_kernel<<<1, 256>>>(out);
}